// round 10
// baseline (speedup 1.0000x reference)
#include <cuda_runtime.h>
#include <cuda_bf16.h>
#include <cuda.h>
#include <cstdint>
#include <dlfcn.h>

#define B_ 8
#define N_ 4096
#define C_ 1024
#define H_ 16
#define SCALE_ 0.125f
#define M_ (B_ * N_)          // 32768 rows
#define K2_ 2048              // stored split K for 1024-wide operands

// ---------------- scratch ----------------
__device__ __align__(16) __nv_bfloat16 g_x2[(size_t)M_ * K2_];          // x split (hi|lo)
__device__ __align__(16) __nv_bfloat16 g_xt2[(size_t)B_ * C_ * 8192];   // x^T split per b
__device__ __align__(16) __nv_bfloat16 g_w2[3][(size_t)C_ * K2_];       // Wq, Wv, Wp split
__device__ __align__(16) __nv_bfloat16 g_g2[(size_t)B_ * C_ * K2_];     // G split
__device__ float g_T[(size_t)B_ * C_ * C_];                             // T = Wq G per b
__device__ __align__(16) __nv_bfloat16 g_v2[(size_t)M_ * K2_];          // V split (hi|lo)
__device__ float g_p[(size_t)128 * 4096];                               // softmaxed P
__device__ __align__(16) __nv_bfloat16 g_o2[(size_t)M_ * K2_];          // attn out split

// ---------------- helpers ----------------
__device__ __forceinline__ uint32_t smem_u32(const void* p) {
    uint32_t a;
    asm("{ .reg .u64 t; cvta.to.shared.u64 t, %1; cvt.u32.u64 %0, t; }" : "=r"(a) : "l"(p));
    return a;
}
__device__ __forceinline__ void ldsm4(uint32_t* r, uint32_t addr) {
    asm volatile("ldmatrix.sync.aligned.m8n8.x4.shared.b16 {%0,%1,%2,%3}, [%4];"
                 : "=r"(r[0]), "=r"(r[1]), "=r"(r[2]), "=r"(r[3]) : "r"(addr));
}
__device__ __forceinline__ void mma16816(float* d, const uint32_t* a, uint32_t b0, uint32_t b1) {
    asm volatile("mma.sync.aligned.m16n8k16.row.col.f32.bf16.bf16.f32 "
                 "{%0,%1,%2,%3}, {%4,%5,%6,%7}, {%8,%9}, {%0,%1,%2,%3};"
                 : "+f"(d[0]), "+f"(d[1]), "+f"(d[2]), "+f"(d[3])
                 : "r"(a[0]), "r"(a[1]), "r"(a[2]), "r"(a[3]), "r"(b0), "r"(b1));
}
__device__ __forceinline__ void mbar_init(uint32_t a, uint32_t cnt) {
    asm volatile("mbarrier.init.shared.b64 [%0], %1;" :: "r"(a), "r"(cnt) : "memory");
}
__device__ __forceinline__ void mbar_wait(uint32_t a, uint32_t parity) {
    asm volatile(
        "{\n\t.reg .pred P;\n\t"
        "W_%=:\n\t"
        "mbarrier.try_wait.parity.acquire.cta.shared::cta.b64 P, [%0], %1, 0x989680;\n\t"
        "@P bra D_%=;\n\t"
        "bra W_%=;\n\t"
        "D_%=:\n\t}"
        :: "r"(a), "r"(parity) : "memory");
}
__device__ __forceinline__ void tma2d(uint32_t smem, const CUtensorMap* tm,
                                      int cx, int cy, uint32_t mbar) {
    asm volatile("cp.async.bulk.tensor.2d.shared::cta.global.tile.mbarrier::complete_tx::bytes "
                 "[%0], [%1, {%2, %3}], [%4];"
                 :: "r"(smem), "l"(tm), "r"(cx), "r"(cy), "r"(mbar) : "memory");
}
__device__ __forceinline__ unsigned long long pk2(float x, float y) {
    unsigned long long r;
    asm("mov.b64 %0, {%1, %2};" : "=l"(r)
        : "r"(__float_as_uint(x)), "r"(__float_as_uint(y)));
    return r;
}
__device__ __forceinline__ void fma2(unsigned long long& c, unsigned long long a,
                                     unsigned long long b) {
    asm("fma.rn.f32x2 %0, %1, %2, %0;" : "+l"(c) : "l"(a), "l"(b));
}
__device__ __forceinline__ float2 upk2(unsigned long long v) {
    unsigned int lo, hi;
    asm("mov.b64 {%0, %1}, %2;" : "=r"(lo), "=r"(hi) : "l"(v));
    return make_float2(__uint_as_float(lo), __uint_as_float(hi));
}
__device__ __forceinline__ void split1(float v, __nv_bfloat16& hi, __nv_bfloat16& lo) {
    hi = __float2bfloat16(v);
    lo = __float2bfloat16(v - __bfloat162float(hi));
}

// ---------------- split fp32 -> [hi | lo] bf16 (rows of 1024) ----------------
__global__ void split_kernel(const float4* __restrict__ in, __nv_bfloat16* __restrict__ out,
                             int n4) {
    int i = blockIdx.x * blockDim.x + threadIdx.x;
    if (i >= n4) return;
    int r = i >> 8;
    int c = (i & 255) << 2;
    float4 v = in[i];
    __nv_bfloat16 hi[4], lo[4];
    split1(v.x, hi[0], lo[0]); split1(v.y, hi[1], lo[1]);
    split1(v.z, hi[2], lo[2]); split1(v.w, hi[3], lo[3]);
    *reinterpret_cast<uint2*>(out + (size_t)r * K2_ + c) = *reinterpret_cast<uint2*>(hi);
    *reinterpret_cast<uint2*>(out + (size_t)r * K2_ + 1024 + c) = *reinterpret_cast<uint2*>(lo);
}

// ---------------- fused x prep (vectorized 64x64 tiles): x2 + xt2 ----------------
__global__ __launch_bounds__(256) void prep_x(const float* __restrict__ x,
                                              __nv_bfloat16* __restrict__ x2,
                                              __nv_bfloat16* __restrict__ xt) {
    __shared__ float tile[64][65];
    const int b = blockIdx.z;
    const int n0 = blockIdx.x * 64, c0 = blockIdx.y * 64;
    const int tid = threadIdx.x;
    const float* xb = x + ((size_t)b * 4096 + n0) * 1024 + c0;
    {
        int r = tid >> 4, q = tid & 15;
#pragma unroll
        for (int k = 0; k < 4; k++) {
            int rr = r + k * 16;
            float4 v = *reinterpret_cast<const float4*>(xb + (size_t)rr * 1024 + q * 4);
            tile[rr][q * 4 + 0] = v.x; tile[rr][q * 4 + 1] = v.y;
            tile[rr][q * 4 + 2] = v.z; tile[rr][q * 4 + 3] = v.w;
        }
    }
    __syncthreads();
    const int row = tid >> 2, part = tid & 3;
    {   // x2: rows = tokens, cols = channels
        __nv_bfloat16 hi[16], lo[16];
#pragma unroll
        for (int j = 0; j < 16; j++) split1(tile[row][part * 16 + j], hi[j], lo[j]);
        __nv_bfloat16* dst = x2 + ((size_t)b * 4096 + n0 + row) * K2_ + c0 + part * 16;
        *reinterpret_cast<uint4*>(dst)        = *reinterpret_cast<uint4*>(hi);
        *reinterpret_cast<uint4*>(dst + 8)    = *reinterpret_cast<uint4*>(hi + 8);
        *reinterpret_cast<uint4*>(dst + 1024) = *reinterpret_cast<uint4*>(lo);
        *reinterpret_cast<uint4*>(dst + 1032) = *reinterpret_cast<uint4*>(lo + 8);
    }
    {   // xt: rows = channels, cols = tokens
        __nv_bfloat16 hi[16], lo[16];
#pragma unroll
        for (int j = 0; j < 16; j++) split1(tile[part * 16 + j][row], hi[j], lo[j]);
        __nv_bfloat16* dst = xt + (size_t)b * C_ * 8192 + (size_t)(c0 + row) * 8192 + n0 + part * 16;
        *reinterpret_cast<uint4*>(dst)        = *reinterpret_cast<uint4*>(hi);
        *reinterpret_cast<uint4*>(dst + 8)    = *reinterpret_cast<uint4*>(hi + 8);
        *reinterpret_cast<uint4*>(dst + 4096) = *reinterpret_cast<uint4*>(lo);
        *reinterpret_cast<uint4*>(dst + 4104) = *reinterpret_cast<uint4*>(lo + 8);
    }
}

// ---------------- TMA HMMA split-precision GEMM ----------------
// CMAP 0: K=1024 op (48 chunks). CMAP 1: Gram K=4096 (192 chunks, cols=8192).
// SYM: triangular tile grid (A==B). GOUT: epilogue writes split-bf16 (mirror only if SYM).
#define STAGE_BYTES 32768
#define GSMEM_SZ (3 * STAGE_BYTES + 64)

template <int CMAP, int NCH, bool SYM, bool BIAS, bool GOUT>
__global__ __launch_bounds__(256, 2) void gemm_tma(
    const __grid_constant__ CUtensorMap tmA, const __grid_constant__ CUtensorMap tmB,
    const float* __restrict__ bias, void* __restrict__ Cptr,
    int aBatchRows, int bBatchRows, size_t cBatch)
{
    extern __shared__ char smem[];
    const uint32_t sb = smem_u32(smem);
    const uint32_t mbb = sb + 3 * STAGE_BYTES;
    const int tid = threadIdx.x, lane = tid & 31, wid = tid >> 5;
    const int wm = wid & 3, wn = wid >> 2;                 // 4 x 2 warp grid (32x64)
    const int z = blockIdx.z;
    int bm, bn;
    if (SYM) {
        int idx = blockIdx.x;
        int ti = (int)floorf((sqrtf(8.f * idx + 1.f) - 1.f) * 0.5f);
        while ((ti + 1) * (ti + 2) / 2 <= idx) ti++;
        while (ti * (ti + 1) / 2 > idx) ti--;
        int tj = idx - ti * (ti + 1) / 2;
        bm = ti * 128; bn = tj * 128;
    } else {
        bm = blockIdx.y * 128;
        bn = blockIdx.x * 128;
    }
    const int cyA = z * aBatchRows + bm;
    const int cyB = z * bBatchRows + bn;

    const int qrow = lane & 15;
    const uint32_t khalf = (uint32_t)((lane >> 4) << 4);
    const uint32_t axor = (uint32_t)((qrow & 7) << 4);

    float acc[2][8][4];
#pragma unroll
    for (int mf = 0; mf < 2; mf++)
#pragma unroll
        for (int nf = 0; nf < 8; nf++)
#pragma unroll
            for (int j = 0; j < 4; j++) acc[mf][nf][j] = 0.f;

    auto kA = [](int i) -> int {
        if (CMAP == 0) return (i < 32 ? i : i - 32) * 64;
        int t = i >> 6, j = i & 63;
        return j * 64 + (t == 1 ? 4096 : 0);
    };
    auto kB = [](int i) -> int {
        if (CMAP == 0) return (i < 16 ? i : i - 16) * 64;
        int t = i >> 6, j = i & 63;
        return j * 64 + (t == 2 ? 4096 : 0);
    };

    if (tid == 0) {
#pragma unroll
        for (int s = 0; s < 3; s++) mbar_init(mbb + s * 8, 1);
    }
    __syncthreads();

    auto issue = [&](int i) {
        uint32_t st = sb + (uint32_t)(i % 3) * STAGE_BYTES;
        uint32_t mb = mbb + (uint32_t)(i % 3) * 8;
        asm volatile("mbarrier.arrive.expect_tx.shared.b64 _, [%0], %1;"
                     :: "r"(mb), "r"(32768u) : "memory");
        tma2d(st, &tmA, kA(i), cyA, mb);
        tma2d(st + 16384, &tmB, kB(i), cyB, mb);
    };

    if (tid == 0) { issue(0); issue(1); }

    for (int i = 0; i < NCH; i++) {
        mbar_wait(mbb + (i % 3) * 8, (i / 3) & 1);
        __syncthreads();
        if (tid == 0 && i + 2 < NCH) issue(i + 2);

        const uint32_t Ab = sb + (uint32_t)(i % 3) * STAGE_BYTES;
        const uint32_t Bb = Ab + 16384;
#pragma unroll
        for (int ks = 0; ks < 4; ks++) {
            const uint32_t kb = (uint32_t)(ks * 32) + khalf;
            uint32_t af[2][4];
#pragma unroll
            for (int mf = 0; mf < 2; mf++)
                ldsm4(af[mf], Ab + (uint32_t)((wm * 32 + mf * 16 + qrow) * 128) + (kb ^ axor));
#pragma unroll
            for (int np = 0; np < 4; np++) {
                uint32_t r[4];
                ldsm4(r, Bb + (uint32_t)((wn * 64 + np * 16 + qrow) * 128) + (kb ^ axor));
#pragma unroll
                for (int mf = 0; mf < 2; mf++) {
                    mma16816(acc[mf][2 * np + 0], af[mf], r[0], r[2]);
                    mma16816(acc[mf][2 * np + 1], af[mf], r[1], r[3]);
                }
            }
        }
    }

    if (GOUT) {
        __syncthreads();
        float* st = reinterpret_cast<float*>(smem);
#pragma unroll
        for (int mf = 0; mf < 2; mf++) {
            int r0 = wm * 32 + mf * 16 + (lane >> 2);
#pragma unroll
            for (int nf = 0; nf < 8; nf++) {
                int c = wn * 64 + nf * 8 + (lane & 3) * 2;
                st[r0 * 129 + c]       = acc[mf][nf][0];
                st[r0 * 129 + c + 1]   = acc[mf][nf][1];
                st[(r0 + 8) * 129 + c]     = acc[mf][nf][2];
                st[(r0 + 8) * 129 + c + 1] = acc[mf][nf][3];
            }
        }
        __syncthreads();
        __nv_bfloat16* g2o = reinterpret_cast<__nv_bfloat16*>(Cptr) + (size_t)z * C_ * K2_;
        const int r = tid >> 1, cbase = (tid & 1) * 64;
#pragma unroll
        for (int g = 0; g < 8; g++) {
            __nv_bfloat16 hi[8], lo[8];
#pragma unroll
            for (int j = 0; j < 8; j++)
                split1(st[r * 129 + cbase + g * 8 + j], hi[j], lo[j]);
            size_t base = (size_t)(bm + r) * K2_ + bn + cbase + g * 8;
            *reinterpret_cast<uint4*>(g2o + base) = *reinterpret_cast<uint4*>(hi);
            *reinterpret_cast<uint4*>(g2o + base + 1024) = *reinterpret_cast<uint4*>(lo);
        }
        if (SYM && bm != bn) {
#pragma unroll
            for (int g = 0; g < 8; g++) {
                __nv_bfloat16 hi[8], lo[8];
#pragma unroll
                for (int j = 0; j < 8; j++)
                    split1(st[(cbase + g * 8 + j) * 129 + r], hi[j], lo[j]);
                size_t base = (size_t)(bn + r) * K2_ + bm + cbase + g * 8;
                *reinterpret_cast<uint4*>(g2o + base) = *reinterpret_cast<uint4*>(hi);
                *reinterpret_cast<uint4*>(g2o + base + 1024) = *reinterpret_cast<uint4*>(lo);
            }
        }
    } else {
        float* Cz = reinterpret_cast<float*>(Cptr) + (size_t)z * cBatch;
#pragma unroll
        for (int mf = 0; mf < 2; mf++) {
            const size_t row0 = (size_t)bm + wm * 32 + mf * 16 + (lane >> 2);
#pragma unroll
            for (int nf = 0; nf < 8; nf++) {
                const int col = bn + wn * 64 + nf * 8 + (lane & 3) * 2;
                float bx = 0.f, by = 0.f;
                if (BIAS) { bx = bias[col]; by = bias[col + 1]; }
                *reinterpret_cast<float2*>(Cz + row0 * C_ + col) =
                    make_float2(acc[mf][nf][0] + bx, acc[mf][nf][1] + by);
                *reinterpret_cast<float2*>(Cz + (row0 + 8) * C_ + col) =
                    make_float2(acc[mf][nf][2] + bx, acc[mf][nf][3] + by);
            }
        }
    }
}

// ---------------- attn_mid: S = T_h Wk_h^T (fp32), softmax -> P ----------------
__global__ __launch_bounds__(256) void attn_mid(const float* __restrict__ T,
                                                const float* __restrict__ Wk,
                                                float* __restrict__ P)
{
    __shared__ float Ts[64][68];
    __shared__ float Wks[64][68];
    const int tid = threadIdx.x;
    const int tx = tid & 15, ty = tid >> 4;
    const int bh = blockIdx.x, b = bh >> 4, h = bh & 15;
    const float* Tb  = T + ((size_t)b << 20) + (size_t)(h * 64) * 1024;
    const float* Wkb = Wk + (size_t)(h * 64) * 1024;

    unsigned long long s2[4][2];
#pragma unroll
    for (int i = 0; i < 4; i++) { s2[i][0] = 0ull; s2[i][1] = 0ull; }

    for (int c0 = 0; c0 < 1024; c0 += 64) {
#pragma unroll
        for (int t = 0; t < 4; t++) {
            int fid = tid + t * 256;
            int r  = fid >> 4;
            int c4 = (fid & 15) << 2;
            float4 a = *reinterpret_cast<const float4*>(Tb + (size_t)r * 1024 + c0 + c4);
            Ts[c4 + 0][r] = a.x; Ts[c4 + 1][r] = a.y;
            Ts[c4 + 2][r] = a.z; Ts[c4 + 3][r] = a.w;
            float4 w = *reinterpret_cast<const float4*>(Wkb + (size_t)r * 1024 + c0 + c4);
            Wks[c4 + 0][r] = w.x; Wks[c4 + 1][r] = w.y;
            Wks[c4 + 2][r] = w.z; Wks[c4 + 3][r] = w.w;
        }
        __syncthreads();
#pragma unroll 8
        for (int cc = 0; cc < 64; cc++) {
            float4 a  = *reinterpret_cast<const float4*>(&Ts[cc][tx * 4]);
            float4 bk = *reinterpret_cast<const float4*>(&Wks[cc][ty * 4]);
            unsigned long long e0 = pk2(bk.x, bk.y), e1 = pk2(bk.z, bk.w);
            float av[4] = {a.x, a.y, a.z, a.w};
#pragma unroll
            for (int i = 0; i < 4; i++) {
                unsigned long long ad = pk2(av[i], av[i]);
                fma2(s2[i][0], ad, e0);
                fma2(s2[i][1], ad, e1);
            }
        }
        __syncthreads();
    }

    float* Ss = &Ts[0][0];
#pragma unroll
    for (int i = 0; i < 4; i++) {
        float2 u0 = upk2(s2[i][0]), u1 = upk2(s2[i][1]);
        *reinterpret_cast<float4*>(Ss + (tx * 4 + i) * 64 + ty * 4) =
            make_float4(u0.x * SCALE_, u0.y * SCALE_, u1.x * SCALE_, u1.y * SCALE_);
    }
    __syncthreads();

    {
        int warp = tid >> 5, lane = tid & 31;
        float* p = P + (size_t)bh * 4096;
        for (int r = warp; r < 64; r += 8) {
            float v0 = Ss[r * 64 + lane], v1 = Ss[r * 64 + lane + 32];
            float m = fmaxf(v0, v1);
#pragma unroll
            for (int off = 16; off; off >>= 1) m = fmaxf(m, __shfl_xor_sync(0xffffffffu, m, off));
            float e0 = expf(v0 - m), e1 = expf(v1 - m);
            float ssum = e0 + e1;
#pragma unroll
            for (int off = 16; off; off >>= 1) ssum += __shfl_xor_sync(0xffffffffu, ssum, off);
            float inv = 1.0f / ssum;
            p[r * 64 + lane] = e0 * inv;
            p[r * 64 + lane + 32] = e1 * inv;
        }
    }
}

// ---------------- attn_pv: O-chunk = P * V-chunk (V read as split bf16) ----------------
__global__ __launch_bounds__(256) void attn_pv(const __nv_bfloat16* __restrict__ V2,
                                               const float* __restrict__ P,
                                               __nv_bfloat16* __restrict__ O2)
{
    __shared__ float Qs[64][64];
    __shared__ float Ks[64][68];
    const int tid = threadIdx.x;
    const int tx = tid & 15, ty = tid >> 4;
    const int bh = blockIdx.x >> 2, ch = blockIdx.x & 3;
    const int b = bh >> 4, h = bh & 15;
    const int nbase = ch * 1024;
    const __nv_bfloat16* Vb = V2 + ((size_t)b * 4096 + nbase) * (size_t)K2_ + h * 64;

    {
        const float4* ps = reinterpret_cast<const float4*>(P + (size_t)bh * 4096);
#pragma unroll
        for (int t = 0; t < 4; t++) {
            int fid = tid + t * 256;
            *reinterpret_cast<float4*>(&Qs[fid >> 4][(fid & 15) << 2]) = ps[fid];
        }
    }
    __syncthreads();

    for (int n0 = 0; n0 < 1024; n0 += 64) {
#pragma unroll
        for (int t = 0; t < 4; t++) {
            int fid = tid + t * 256;
            int nl  = fid >> 4;
            int e4  = (fid & 15) << 2;
            const __nv_bfloat16* src = Vb + (size_t)(n0 + nl) * K2_ + e4;
            const __nv_bfloat162* sh = reinterpret_cast<const __nv_bfloat162*>(src);
            const __nv_bfloat162* sl = reinterpret_cast<const __nv_bfloat162*>(src + 1024);
            __nv_bfloat162 h0 = sh[0], h1 = sh[1], l0 = sl[0], l1 = sl[1];
            Ks[e4 + 0][nl] = __bfloat162float(h0.x) + __bfloat162float(l0.x);
            Ks[e4 + 1][nl] = __bfloat162float(h0.y) + __bfloat162float(l0.y);
            Ks[e4 + 2][nl] = __bfloat162float(h1.x) + __bfloat162float(l1.x);
            Ks[e4 + 3][nl] = __bfloat162float(h1.y) + __bfloat162float(l1.y);
        }
        __syncthreads();
        unsigned long long o2a[4][2];
#pragma unroll
        for (int i = 0; i < 4; i++) { o2a[i][0] = 0ull; o2a[i][1] = 0ull; }
#pragma unroll 4
        for (int e = 0; e < 64; e += 4) {
            float4 p0 = *reinterpret_cast<const float4*>(&Qs[ty * 4 + 0][e]);
            float4 p1 = *reinterpret_cast<const float4*>(&Qs[ty * 4 + 1][e]);
            float4 p2 = *reinterpret_cast<const float4*>(&Qs[ty * 4 + 2][e]);
            float4 p3 = *reinterpret_cast<const float4*>(&Qs[ty * 4 + 3][e]);
            float4 v0 = *reinterpret_cast<const float4*>(&Ks[e + 0][tx * 4]);
            float4 v1 = *reinterpret_cast<const float4*>(&Ks[e + 1][tx * 4]);
            float4 v2 = *reinterpret_cast<const float4*>(&Ks[e + 2][tx * 4]);
            float4 v3 = *reinterpret_cast<const float4*>(&Ks[e + 3][tx * 4]);
            unsigned long long vq[4][2] = {
                {pk2(v0.x, v0.y), pk2(v0.z, v0.w)},
                {pk2(v1.x, v1.y), pk2(v1.z, v1.w)},
                {pk2(v2.x, v2.y), pk2(v2.z, v2.w)},
                {pk2(v3.x, v3.y), pk2(v3.z, v3.w)}};
            float pr[4][4] = {{p0.x, p0.y, p0.z, p0.w},
                              {p1.x, p1.y, p1.z, p1.w},
                              {p2.x, p2.y, p2.z, p2.w},
                              {p3.x, p3.y, p3.z, p3.w}};
#pragma unroll
            for (int i = 0; i < 4; i++) {
#pragma unroll
                for (int q = 0; q < 4; q++) {
                    unsigned long long pd = pk2(pr[i][q], pr[i][q]);
                    fma2(o2a[i][0], pd, vq[q][0]);
                    fma2(o2a[i][1], pd, vq[q][1]);
                }
            }
        }
        __syncthreads();
#pragma unroll
        for (int i = 0; i < 4; i++) {
            int d = ty * 4 + i;
            size_t row = (size_t)b * 4096 + (size_t)d * 64 + h * 4 + ch;
            int col = n0 + tx * 4;
            float2 u0 = upk2(o2a[i][0]), u1 = upk2(o2a[i][1]);
            float vv[4] = {u0.x, u0.y, u1.x, u1.y};
            __nv_bfloat16 hi[4], lo[4];
#pragma unroll
            for (int j = 0; j < 4; j++) split1(vv[j], hi[j], lo[j]);
            *reinterpret_cast<uint2*>(O2 + row * K2_ + col) = *reinterpret_cast<uint2*>(hi);
            *reinterpret_cast<uint2*>(O2 + row * K2_ + 1024 + col) = *reinterpret_cast<uint2*>(lo);
        }
    }
}

// ---------------- host ----------------
typedef CUresult (*EncodeTiledFn)(
    CUtensorMap*, CUtensorMapDataType, cuuint32_t, void*,
    const cuuint64_t*, const cuuint64_t*, const cuuint32_t*, const cuuint32_t*,
    CUtensorMapInterleave, CUtensorMapSwizzle, CUtensorMapL2promotion,
    CUtensorMapFloatOOBfill);

static void make_tm(EncodeTiledFn enc, CUtensorMap* tm, void* ptr,
                    unsigned long long rows, unsigned long long cols) {
    cuuint64_t dims[2] = {cols, rows};
    cuuint64_t strides[1] = {cols * 2};
    cuuint32_t box[2] = {64, 128};
    cuuint32_t es[2] = {1, 1};
    enc(tm, CU_TENSOR_MAP_DATA_TYPE_BFLOAT16, 2, ptr, dims, strides, box, es,
        CU_TENSOR_MAP_INTERLEAVE_NONE, CU_TENSOR_MAP_SWIZZLE_128B,
        CU_TENSOR_MAP_L2_PROMOTION_L2_128B, CU_TENSOR_MAP_FLOAT_OOB_FILL_NONE);
}

extern "C" void kernel_launch(void* const* d_in, const int* in_sizes, int n_in,
                              void* d_out, int out_size)
{
    const float* x  = (const float*)d_in[0];
    const float* Wq = (const float*)d_in[1];
    const float* Wk = (const float*)d_in[2];
    const float* Wv = (const float*)d_in[3];
    const float* Wp = (const float*)d_in[4];
    const float* bp = (const float*)d_in[5];
    float* out = (float*)d_out;

    __nv_bfloat16 *x2, *xt2, *w2, *g2, *v2, *o2;
    float *T, *p;
    cudaGetSymbolAddress((void**)&x2, g_x2);
    cudaGetSymbolAddress((void**)&xt2, g_xt2);
    cudaGetSymbolAddress((void**)&w2, g_w2);
    cudaGetSymbolAddress((void**)&g2, g_g2);
    cudaGetSymbolAddress((void**)&T, g_T);
    cudaGetSymbolAddress((void**)&v2, g_v2);
    cudaGetSymbolAddress((void**)&p, g_p);
    cudaGetSymbolAddress((void**)&o2, g_o2);

    void* h = dlopen("libcuda.so.1", RTLD_NOW | RTLD_GLOBAL);
    if (!h) h = dlopen("libcuda.so", RTLD_NOW | RTLD_GLOBAL);
    EncodeTiledFn enc = (EncodeTiledFn)dlsym(h, "cuTensorMapEncodeTiled");

    const size_t wStride = (size_t)C_ * K2_;
    __nv_bfloat16* wq2 = w2;
    __nv_bfloat16* wv2 = w2 + wStride;
    __nv_bfloat16* wp2 = w2 + 2 * wStride;

    CUtensorMap tm_x2, tm_wq, tm_wv, tm_wp, tm_g2, tm_xt2, tm_o2;
    make_tm(enc, &tm_x2, x2, 32768ull, 2048ull);
    make_tm(enc, &tm_wq, wq2, 1024ull, 2048ull);
    make_tm(enc, &tm_wv, wv2, 1024ull, 2048ull);
    make_tm(enc, &tm_wp, wp2, 1024ull, 2048ull);
    make_tm(enc, &tm_g2, g2, 8192ull, 2048ull);
    make_tm(enc, &tm_xt2, xt2, 8192ull, 8192ull);
    make_tm(enc, &tm_o2, o2, 32768ull, 2048ull);

    auto* kVg = gemm_tma<0, 48, false, false, true>;    // V -> split bf16 out
    auto* kT  = gemm_tma<0, 48, false, false, false>;   // T -> fp32 out
    auto* kF  = gemm_tma<0, 48, false, true,  false>;   // final + bias
    auto* kG  = gemm_tma<1, 192, true, false, true>;    // Gram -> split (+mirror)
    cudaFuncSetAttribute(kVg, cudaFuncAttributeMaxDynamicSharedMemorySize, GSMEM_SZ);
    cudaFuncSetAttribute(kT,  cudaFuncAttributeMaxDynamicSharedMemorySize, GSMEM_SZ);
    cudaFuncSetAttribute(kF,  cudaFuncAttributeMaxDynamicSharedMemorySize, GSMEM_SZ);
    cudaFuncSetAttribute(kG,  cudaFuncAttributeMaxDynamicSharedMemorySize, GSMEM_SZ);

    // prep
    split_kernel<<<(C_ * C_ / 4 + 255) / 256, 256>>>((const float4*)Wq, wq2, C_ * C_ / 4);
    split_kernel<<<(C_ * C_ / 4 + 255) / 256, 256>>>((const float4*)Wv, wv2, C_ * C_ / 4);
    split_kernel<<<(C_ * C_ / 4 + 255) / 256, 256>>>((const float4*)Wp, wp2, C_ * C_ / 4);
    prep_x<<<dim3(64, 16, 8), 256>>>(x, x2, xt2);

    // Gram -> split g2 directly (with mirror)
    kG<<<dim3(36, 1, 8), 256, GSMEM_SZ>>>(tm_xt2, tm_xt2, nullptr, g2, C_, C_, 0);

    // V = X Wv^T (split output)
    kVg<<<dim3(8, 256, 1), 256, GSMEM_SZ>>>(tm_x2, tm_wv, nullptr, v2, 0, 0, 0);

    // T_b = Wq * G_b
    kT<<<dim3(8, 8, 8), 256, GSMEM_SZ>>>(tm_wq, tm_g2, nullptr, T, 0, C_, (size_t)C_ * C_);

    // S + softmax -> P ; then O = P V (split output)
    attn_mid<<<128, 256>>>(T, Wk, p);
    attn_pv<<<512, 256>>>(v2, p, o2);

    // out = O' Wp^T + bp
    kF<<<dim3(8, 256, 1), 256, GSMEM_SZ>>>(tm_o2, tm_wp, bp, out, 0, 0, 0);

    dlclose(h);
}

// round 15
// speedup vs baseline: 1.0314x; 1.0314x over previous
#include <cuda_runtime.h>
#include <cuda_bf16.h>
#include <cuda.h>
#include <cstdint>
#include <dlfcn.h>

#define B_ 8
#define N_ 4096
#define C_ 1024
#define H_ 16
#define SCALE_ 0.125f
#define M_ (B_ * N_)          // 32768 rows
#define K2_ 2048              // stored split K for 1024-wide operands

// ---------------- scratch ----------------
__device__ __align__(16) __nv_bfloat16 g_x2[(size_t)M_ * K2_];          // x split (hi|lo)
__device__ __align__(16) __nv_bfloat16 g_xt2[(size_t)B_ * C_ * 8192];   // x^T split per b
__device__ __align__(16) __nv_bfloat16 g_w2[3][(size_t)C_ * K2_];       // Wq, Wv, Wp split
__device__ __align__(16) __nv_bfloat16 g_g2[(size_t)B_ * C_ * K2_];     // G split
__device__ float g_T[(size_t)B_ * C_ * C_];                             // T = Wq G per b
__device__ float g_v[(size_t)M_ * C_];                                  // V = X Wv^T (fp32)
__device__ float g_p[(size_t)128 * 4096];                               // softmaxed P
__device__ __align__(16) __nv_bfloat16 g_o2[(size_t)M_ * K2_];          // attn out split

// ---------------- helpers ----------------
__device__ __forceinline__ uint32_t smem_u32(const void* p) {
    uint32_t a;
    asm("{ .reg .u64 t; cvta.to.shared.u64 t, %1; cvt.u32.u64 %0, t; }" : "=r"(a) : "l"(p));
    return a;
}
__device__ __forceinline__ void ldsm4(uint32_t* r, uint32_t addr) {
    asm volatile("ldmatrix.sync.aligned.m8n8.x4.shared.b16 {%0,%1,%2,%3}, [%4];"
                 : "=r"(r[0]), "=r"(r[1]), "=r"(r[2]), "=r"(r[3]) : "r"(addr));
}
__device__ __forceinline__ void mma16816(float* d, const uint32_t* a, uint32_t b0, uint32_t b1) {
    asm volatile("mma.sync.aligned.m16n8k16.row.col.f32.bf16.bf16.f32 "
                 "{%0,%1,%2,%3}, {%4,%5,%6,%7}, {%8,%9}, {%0,%1,%2,%3};"
                 : "+f"(d[0]), "+f"(d[1]), "+f"(d[2]), "+f"(d[3])
                 : "r"(a[0]), "r"(a[1]), "r"(a[2]), "r"(a[3]), "r"(b0), "r"(b1));
}
__device__ __forceinline__ void mbar_init(uint32_t a, uint32_t cnt) {
    asm volatile("mbarrier.init.shared.b64 [%0], %1;" :: "r"(a), "r"(cnt) : "memory");
}
__device__ __forceinline__ void mbar_wait(uint32_t a, uint32_t parity) {
    asm volatile(
        "{\n\t.reg .pred P;\n\t"
        "W_%=:\n\t"
        "mbarrier.try_wait.parity.acquire.cta.shared::cta.b64 P, [%0], %1, 0x989680;\n\t"
        "@P bra D_%=;\n\t"
        "bra W_%=;\n\t"
        "D_%=:\n\t}"
        :: "r"(a), "r"(parity) : "memory");
}
__device__ __forceinline__ void tma2d(uint32_t smem, const CUtensorMap* tm,
                                      int cx, int cy, uint32_t mbar) {
    asm volatile("cp.async.bulk.tensor.2d.shared::cta.global.tile.mbarrier::complete_tx::bytes "
                 "[%0], [%1, {%2, %3}], [%4];"
                 :: "r"(smem), "l"(tm), "r"(cx), "r"(cy), "r"(mbar) : "memory");
}
__device__ __forceinline__ unsigned long long pk2(float x, float y) {
    unsigned long long r;
    asm("mov.b64 %0, {%1, %2};" : "=l"(r)
        : "r"(__float_as_uint(x)), "r"(__float_as_uint(y)));
    return r;
}
__device__ __forceinline__ void fma2(unsigned long long& c, unsigned long long a,
                                     unsigned long long b) {
    asm("fma.rn.f32x2 %0, %1, %2, %0;" : "+l"(c) : "l"(a), "l"(b));
}
__device__ __forceinline__ float2 upk2(unsigned long long v) {
    unsigned int lo, hi;
    asm("mov.b64 {%0, %1}, %2;" : "=r"(lo), "=r"(hi) : "l"(v));
    return make_float2(__uint_as_float(lo), __uint_as_float(hi));
}
__device__ __forceinline__ void split1(float v, __nv_bfloat16& hi, __nv_bfloat16& lo) {
    hi = __float2bfloat16(v);
    lo = __float2bfloat16(v - __bfloat162float(hi));
}

// ---------------- split fp32 -> [hi | lo] bf16 (rows of 1024) ----------------
__global__ void split_kernel(const float4* __restrict__ in, __nv_bfloat16* __restrict__ out,
                             int n4) {
    int i = blockIdx.x * blockDim.x + threadIdx.x;
    if (i >= n4) return;
    int r = i >> 8;
    int c = (i & 255) << 2;
    float4 v = in[i];
    __nv_bfloat16 hi[4], lo[4];
    split1(v.x, hi[0], lo[0]); split1(v.y, hi[1], lo[1]);
    split1(v.z, hi[2], lo[2]); split1(v.w, hi[3], lo[3]);
    *reinterpret_cast<uint2*>(out + (size_t)r * K2_ + c) = *reinterpret_cast<uint2*>(hi);
    *reinterpret_cast<uint2*>(out + (size_t)r * K2_ + 1024 + c) = *reinterpret_cast<uint2*>(lo);
}

// ---------------- fused x prep (vectorized 64x64 tiles): x2 + xt2 ----------------
__global__ __launch_bounds__(256) void prep_x(const float* __restrict__ x,
                                              __nv_bfloat16* __restrict__ x2,
                                              __nv_bfloat16* __restrict__ xt) {
    __shared__ float tile[64][65];
    const int b = blockIdx.z;
    const int n0 = blockIdx.x * 64, c0 = blockIdx.y * 64;
    const int tid = threadIdx.x;
    const float* xb = x + ((size_t)b * 4096 + n0) * 1024 + c0;
    {
        int r = tid >> 4, q = tid & 15;
#pragma unroll
        for (int k = 0; k < 4; k++) {
            int rr = r + k * 16;
            float4 v = *reinterpret_cast<const float4*>(xb + (size_t)rr * 1024 + q * 4);
            tile[rr][q * 4 + 0] = v.x; tile[rr][q * 4 + 1] = v.y;
            tile[rr][q * 4 + 2] = v.z; tile[rr][q * 4 + 3] = v.w;
        }
    }
    __syncthreads();
    const int row = tid >> 2, part = tid & 3;
    {   // x2: rows = tokens, cols = channels
        __nv_bfloat16 hi[16], lo[16];
#pragma unroll
        for (int j = 0; j < 16; j++) split1(tile[row][part * 16 + j], hi[j], lo[j]);
        __nv_bfloat16* dst = x2 + ((size_t)b * 4096 + n0 + row) * K2_ + c0 + part * 16;
        *reinterpret_cast<uint4*>(dst)        = *reinterpret_cast<uint4*>(hi);
        *reinterpret_cast<uint4*>(dst + 8)    = *reinterpret_cast<uint4*>(hi + 8);
        *reinterpret_cast<uint4*>(dst + 1024) = *reinterpret_cast<uint4*>(lo);
        *reinterpret_cast<uint4*>(dst + 1032) = *reinterpret_cast<uint4*>(lo + 8);
    }
    {   // xt: rows = channels, cols = tokens
        __nv_bfloat16 hi[16], lo[16];
#pragma unroll
        for (int j = 0; j < 16; j++) split1(tile[part * 16 + j][row], hi[j], lo[j]);
        __nv_bfloat16* dst = xt + (size_t)b * C_ * 8192 + (size_t)(c0 + row) * 8192 + n0 + part * 16;
        *reinterpret_cast<uint4*>(dst)        = *reinterpret_cast<uint4*>(hi);
        *reinterpret_cast<uint4*>(dst + 8)    = *reinterpret_cast<uint4*>(hi + 8);
        *reinterpret_cast<uint4*>(dst + 4096) = *reinterpret_cast<uint4*>(lo);
        *reinterpret_cast<uint4*>(dst + 4104) = *reinterpret_cast<uint4*>(lo + 8);
    }
}

// ---------------- TMA HMMA split-precision GEMM ----------------
// CMAP 0: K=1024 op (48 chunks). CMAP 1: Gram K=4096 (192 chunks, cols=8192).
// SYM: triangular tile grid (A==B). GOUT: epilogue writes split-bf16 (mirror only if SYM).
#define STAGE_BYTES 32768
#define GSMEM_SZ (3 * STAGE_BYTES + 64)

template <int CMAP, int NCH, bool SYM, bool BIAS, bool GOUT>
__global__ __launch_bounds__(256, 2) void gemm_tma(
    const __grid_constant__ CUtensorMap tmA, const __grid_constant__ CUtensorMap tmB,
    const float* __restrict__ bias, void* __restrict__ Cptr,
    int aBatchRows, int bBatchRows, size_t cBatch)
{
    extern __shared__ char smem[];
    const uint32_t sb = smem_u32(smem);
    const uint32_t mbb = sb + 3 * STAGE_BYTES;
    const int tid = threadIdx.x, lane = tid & 31, wid = tid >> 5;
    const int wm = wid & 3, wn = wid >> 2;                 // 4 x 2 warp grid (32x64)
    const int z = blockIdx.z;
    int bm, bn;
    if (SYM) {
        int idx = blockIdx.x;
        int ti = (int)floorf((sqrtf(8.f * idx + 1.f) - 1.f) * 0.5f);
        while ((ti + 1) * (ti + 2) / 2 <= idx) ti++;
        while (ti * (ti + 1) / 2 > idx) ti--;
        int tj = idx - ti * (ti + 1) / 2;
        bm = ti * 128; bn = tj * 128;
    } else {
        bm = blockIdx.y * 128;
        bn = blockIdx.x * 128;
    }
    const int cyA = z * aBatchRows + bm;
    const int cyB = z * bBatchRows + bn;

    const int qrow = lane & 15;
    const uint32_t khalf = (uint32_t)((lane >> 4) << 4);
    const uint32_t axor = (uint32_t)((qrow & 7) << 4);

    float acc[2][8][4];
#pragma unroll
    for (int mf = 0; mf < 2; mf++)
#pragma unroll
        for (int nf = 0; nf < 8; nf++)
#pragma unroll
            for (int j = 0; j < 4; j++) acc[mf][nf][j] = 0.f;

    auto kA = [](int i) -> int {
        if (CMAP == 0) return (i < 32 ? i : i - 32) * 64;
        int t = i >> 6, j = i & 63;
        return j * 64 + (t == 1 ? 4096 : 0);
    };
    auto kB = [](int i) -> int {
        if (CMAP == 0) return (i < 16 ? i : i - 16) * 64;
        int t = i >> 6, j = i & 63;
        return j * 64 + (t == 2 ? 4096 : 0);
    };

    if (tid == 0) {
#pragma unroll
        for (int s = 0; s < 3; s++) mbar_init(mbb + s * 8, 1);
    }
    __syncthreads();

    auto issue = [&](int i) {
        uint32_t st = sb + (uint32_t)(i % 3) * STAGE_BYTES;
        uint32_t mb = mbb + (uint32_t)(i % 3) * 8;
        asm volatile("mbarrier.arrive.expect_tx.shared.b64 _, [%0], %1;"
                     :: "r"(mb), "r"(32768u) : "memory");
        tma2d(st, &tmA, kA(i), cyA, mb);
        tma2d(st + 16384, &tmB, kB(i), cyB, mb);
    };

    if (tid == 0) { issue(0); issue(1); }

    for (int i = 0; i < NCH; i++) {
        mbar_wait(mbb + (i % 3) * 8, (i / 3) & 1);
        __syncthreads();
        if (tid == 0 && i + 2 < NCH) issue(i + 2);

        const uint32_t Ab = sb + (uint32_t)(i % 3) * STAGE_BYTES;
        const uint32_t Bb = Ab + 16384;
#pragma unroll
        for (int ks = 0; ks < 4; ks++) {
            const uint32_t kb = (uint32_t)(ks * 32) + khalf;
            uint32_t af[2][4];
#pragma unroll
            for (int mf = 0; mf < 2; mf++)
                ldsm4(af[mf], Ab + (uint32_t)((wm * 32 + mf * 16 + qrow) * 128) + (kb ^ axor));
#pragma unroll
            for (int np = 0; np < 4; np++) {
                uint32_t r[4];
                ldsm4(r, Bb + (uint32_t)((wn * 64 + np * 16 + qrow) * 128) + (kb ^ axor));
#pragma unroll
                for (int mf = 0; mf < 2; mf++) {
                    mma16816(acc[mf][2 * np + 0], af[mf], r[0], r[2]);
                    mma16816(acc[mf][2 * np + 1], af[mf], r[1], r[3]);
                }
            }
        }
    }

    if (GOUT) {
        __syncthreads();
        float* st = reinterpret_cast<float*>(smem);
#pragma unroll
        for (int mf = 0; mf < 2; mf++) {
            int r0 = wm * 32 + mf * 16 + (lane >> 2);
#pragma unroll
            for (int nf = 0; nf < 8; nf++) {
                int c = wn * 64 + nf * 8 + (lane & 3) * 2;
                st[r0 * 129 + c]       = acc[mf][nf][0];
                st[r0 * 129 + c + 1]   = acc[mf][nf][1];
                st[(r0 + 8) * 129 + c]     = acc[mf][nf][2];
                st[(r0 + 8) * 129 + c + 1] = acc[mf][nf][3];
            }
        }
        __syncthreads();
        __nv_bfloat16* g2o = reinterpret_cast<__nv_bfloat16*>(Cptr) + (size_t)z * C_ * K2_;
        const int r = tid >> 1, cbase = (tid & 1) * 64;
#pragma unroll
        for (int g = 0; g < 8; g++) {
            __nv_bfloat16 hi[8], lo[8];
#pragma unroll
            for (int j = 0; j < 8; j++)
                split1(st[r * 129 + cbase + g * 8 + j], hi[j], lo[j]);
            size_t base = (size_t)(bm + r) * K2_ + bn + cbase + g * 8;
            *reinterpret_cast<uint4*>(g2o + base) = *reinterpret_cast<uint4*>(hi);
            *reinterpret_cast<uint4*>(g2o + base + 1024) = *reinterpret_cast<uint4*>(lo);
        }
        if (SYM && bm != bn) {
#pragma unroll
            for (int g = 0; g < 8; g++) {
                __nv_bfloat16 hi[8], lo[8];
#pragma unroll
                for (int j = 0; j < 8; j++)
                    split1(st[(cbase + g * 8 + j) * 129 + r], hi[j], lo[j]);
                size_t base = (size_t)(bn + r) * K2_ + bm + cbase + g * 8;
                *reinterpret_cast<uint4*>(g2o + base) = *reinterpret_cast<uint4*>(hi);
                *reinterpret_cast<uint4*>(g2o + base + 1024) = *reinterpret_cast<uint4*>(lo);
            }
        }
    } else {
        float* Cz = reinterpret_cast<float*>(Cptr) + (size_t)z * cBatch;
#pragma unroll
        for (int mf = 0; mf < 2; mf++) {
            const size_t row0 = (size_t)bm + wm * 32 + mf * 16 + (lane >> 2);
#pragma unroll
            for (int nf = 0; nf < 8; nf++) {
                const int col = bn + wn * 64 + nf * 8 + (lane & 3) * 2;
                float bx = 0.f, by = 0.f;
                if (BIAS) { bx = bias[col]; by = bias[col + 1]; }
                *reinterpret_cast<float2*>(Cz + row0 * C_ + col) =
                    make_float2(acc[mf][nf][0] + bx, acc[mf][nf][1] + by);
                *reinterpret_cast<float2*>(Cz + (row0 + 8) * C_ + col) =
                    make_float2(acc[mf][nf][2] + bx, acc[mf][nf][3] + by);
            }
        }
    }
}

// ---------------- attn_mid: S = T_h Wk_h^T (fp32), softmax -> P ----------------
__global__ __launch_bounds__(256) void attn_mid(const float* __restrict__ T,
                                                const float* __restrict__ Wk,
                                                float* __restrict__ P)
{
    __shared__ float Ts[64][68];
    __shared__ float Wks[64][68];
    const int tid = threadIdx.x;
    const int tx = tid & 15, ty = tid >> 4;
    const int bh = blockIdx.x, b = bh >> 4, h = bh & 15;
    const float* Tb  = T + ((size_t)b << 20) + (size_t)(h * 64) * 1024;
    const float* Wkb = Wk + (size_t)(h * 64) * 1024;

    unsigned long long s2[4][2];
#pragma unroll
    for (int i = 0; i < 4; i++) { s2[i][0] = 0ull; s2[i][1] = 0ull; }

    for (int c0 = 0; c0 < 1024; c0 += 64) {
#pragma unroll
        for (int t = 0; t < 4; t++) {
            int fid = tid + t * 256;
            int r  = fid >> 4;
            int c4 = (fid & 15) << 2;
            float4 a = *reinterpret_cast<const float4*>(Tb + (size_t)r * 1024 + c0 + c4);
            Ts[c4 + 0][r] = a.x; Ts[c4 + 1][r] = a.y;
            Ts[c4 + 2][r] = a.z; Ts[c4 + 3][r] = a.w;
            float4 w = *reinterpret_cast<const float4*>(Wkb + (size_t)r * 1024 + c0 + c4);
            Wks[c4 + 0][r] = w.x; Wks[c4 + 1][r] = w.y;
            Wks[c4 + 2][r] = w.z; Wks[c4 + 3][r] = w.w;
        }
        __syncthreads();
#pragma unroll 8
        for (int cc = 0; cc < 64; cc++) {
            float4 a  = *reinterpret_cast<const float4*>(&Ts[cc][tx * 4]);
            float4 bk = *reinterpret_cast<const float4*>(&Wks[cc][ty * 4]);
            unsigned long long e0 = pk2(bk.x, bk.y), e1 = pk2(bk.z, bk.w);
            float av[4] = {a.x, a.y, a.z, a.w};
#pragma unroll
            for (int i = 0; i < 4; i++) {
                unsigned long long ad = pk2(av[i], av[i]);
                fma2(s2[i][0], ad, e0);
                fma2(s2[i][1], ad, e1);
            }
        }
        __syncthreads();
    }

    float* Ss = &Ts[0][0];
#pragma unroll
    for (int i = 0; i < 4; i++) {
        float2 u0 = upk2(s2[i][0]), u1 = upk2(s2[i][1]);
        *reinterpret_cast<float4*>(Ss + (tx * 4 + i) * 64 + ty * 4) =
            make_float4(u0.x * SCALE_, u0.y * SCALE_, u1.x * SCALE_, u1.y * SCALE_);
    }
    __syncthreads();

    {
        int warp = tid >> 5, lane = tid & 31;
        float* p = P + (size_t)bh * 4096;
        for (int r = warp; r < 64; r += 8) {
            float v0 = Ss[r * 64 + lane], v1 = Ss[r * 64 + lane + 32];
            float m = fmaxf(v0, v1);
#pragma unroll
            for (int off = 16; off; off >>= 1) m = fmaxf(m, __shfl_xor_sync(0xffffffffu, m, off));
            float e0 = expf(v0 - m), e1 = expf(v1 - m);
            float ssum = e0 + e1;
#pragma unroll
            for (int off = 16; off; off >>= 1) ssum += __shfl_xor_sync(0xffffffffu, ssum, off);
            float inv = 1.0f / ssum;
            p[r * 64 + lane] = e0 * inv;
            p[r * 64 + lane + 32] = e1 * inv;
        }
    }
}

// ---------------- attn_pv: O-chunk = P * V-chunk, write split bf16 ----------------
__global__ __launch_bounds__(256) void attn_pv(const float* __restrict__ Vbuf,
                                               const float* __restrict__ P,
                                               __nv_bfloat16* __restrict__ O2)
{
    __shared__ float Qs[64][64];
    __shared__ float Ks[64][68];
    const int tid = threadIdx.x;
    const int tx = tid & 15, ty = tid >> 4;
    const int bh = blockIdx.x >> 2, ch = blockIdx.x & 3;
    const int b = bh >> 4, h = bh & 15;
    const float* V = Vbuf + (size_t)b * (N_ * C_) + h * 64;
    const int nbase = ch * 1024;

    {
        const float4* ps = reinterpret_cast<const float4*>(P + (size_t)bh * 4096);
#pragma unroll
        for (int t = 0; t < 4; t++) {
            int fid = tid + t * 256;
            *reinterpret_cast<float4*>(&Qs[fid >> 4][(fid & 15) << 2]) = ps[fid];
        }
    }
    __syncthreads();

    for (int n0 = 0; n0 < 1024; n0 += 64) {
#pragma unroll
        for (int t = 0; t < 4; t++) {
            int fid = tid + t * 256;
            int nl  = fid >> 4;
            int e4  = (fid & 15) << 2;
            float4 v = *reinterpret_cast<const float4*>(V + (size_t)(nbase + n0 + nl) * C_ + e4);
            Ks[e4 + 0][nl] = v.x; Ks[e4 + 1][nl] = v.y;
            Ks[e4 + 2][nl] = v.z; Ks[e4 + 3][nl] = v.w;
        }
        __syncthreads();
        unsigned long long o2a[4][2];
#pragma unroll
        for (int i = 0; i < 4; i++) { o2a[i][0] = 0ull; o2a[i][1] = 0ull; }
#pragma unroll 4
        for (int e = 0; e < 64; e += 4) {
            float4 p0 = *reinterpret_cast<const float4*>(&Qs[ty * 4 + 0][e]);
            float4 p1 = *reinterpret_cast<const float4*>(&Qs[ty * 4 + 1][e]);
            float4 p2 = *reinterpret_cast<const float4*>(&Qs[ty * 4 + 2][e]);
            float4 p3 = *reinterpret_cast<const float4*>(&Qs[ty * 4 + 3][e]);
            float4 v0 = *reinterpret_cast<const float4*>(&Ks[e + 0][tx * 4]);
            float4 v1 = *reinterpret_cast<const float4*>(&Ks[e + 1][tx * 4]);
            float4 v2 = *reinterpret_cast<const float4*>(&Ks[e + 2][tx * 4]);
            float4 v3 = *reinterpret_cast<const float4*>(&Ks[e + 3][tx * 4]);
            unsigned long long vq[4][2] = {
                {pk2(v0.x, v0.y), pk2(v0.z, v0.w)},
                {pk2(v1.x, v1.y), pk2(v1.z, v1.w)},
                {pk2(v2.x, v2.y), pk2(v2.z, v2.w)},
                {pk2(v3.x, v3.y), pk2(v3.z, v3.w)}};
            float pr[4][4] = {{p0.x, p0.y, p0.z, p0.w},
                              {p1.x, p1.y, p1.z, p1.w},
                              {p2.x, p2.y, p2.z, p2.w},
                              {p3.x, p3.y, p3.z, p3.w}};
#pragma unroll
            for (int i = 0; i < 4; i++) {
#pragma unroll
                for (int q = 0; q < 4; q++) {
                    unsigned long long pd = pk2(pr[i][q], pr[i][q]);
                    fma2(o2a[i][0], pd, vq[q][0]);
                    fma2(o2a[i][1], pd, vq[q][1]);
                }
            }
        }
        __syncthreads();
#pragma unroll
        for (int i = 0; i < 4; i++) {
            int d = ty * 4 + i;
            size_t row = (size_t)b * 4096 + (size_t)d * 64 + h * 4 + ch;
            int col = n0 + tx * 4;
            float2 u0 = upk2(o2a[i][0]), u1 = upk2(o2a[i][1]);
            float vv[4] = {u0.x, u0.y, u1.x, u1.y};
            __nv_bfloat16 hi[4], lo[4];
#pragma unroll
            for (int j = 0; j < 4; j++) split1(vv[j], hi[j], lo[j]);
            *reinterpret_cast<uint2*>(O2 + row * K2_ + col) = *reinterpret_cast<uint2*>(hi);
            *reinterpret_cast<uint2*>(O2 + row * K2_ + 1024 + col) = *reinterpret_cast<uint2*>(lo);
        }
    }
}

// ---------------- host ----------------
typedef CUresult (*EncodeTiledFn)(
    CUtensorMap*, CUtensorMapDataType, cuuint32_t, void*,
    const cuuint64_t*, const cuuint64_t*, const cuuint32_t*, const cuuint32_t*,
    CUtensorMapInterleave, CUtensorMapSwizzle, CUtensorMapL2promotion,
    CUtensorMapFloatOOBfill);

static void make_tm(EncodeTiledFn enc, CUtensorMap* tm, void* ptr,
                    unsigned long long rows, unsigned long long cols) {
    cuuint64_t dims[2] = {cols, rows};
    cuuint64_t strides[1] = {cols * 2};
    cuuint32_t box[2] = {64, 128};
    cuuint32_t es[2] = {1, 1};
    enc(tm, CU_TENSOR_MAP_DATA_TYPE_BFLOAT16, 2, ptr, dims, strides, box, es,
        CU_TENSOR_MAP_INTERLEAVE_NONE, CU_TENSOR_MAP_SWIZZLE_128B,
        CU_TENSOR_MAP_L2_PROMOTION_L2_128B, CU_TENSOR_MAP_FLOAT_OOB_FILL_NONE);
}

extern "C" void kernel_launch(void* const* d_in, const int* in_sizes, int n_in,
                              void* d_out, int out_size)
{
    const float* x  = (const float*)d_in[0];
    const float* Wq = (const float*)d_in[1];
    const float* Wk = (const float*)d_in[2];
    const float* Wv = (const float*)d_in[3];
    const float* Wp = (const float*)d_in[4];
    const float* bp = (const float*)d_in[5];
    float* out = (float*)d_out;

    __nv_bfloat16 *x2, *xt2, *w2, *g2, *o2;
    float *T, *v, *p;
    cudaGetSymbolAddress((void**)&x2, g_x2);
    cudaGetSymbolAddress((void**)&xt2, g_xt2);
    cudaGetSymbolAddress((void**)&w2, g_w2);
    cudaGetSymbolAddress((void**)&g2, g_g2);
    cudaGetSymbolAddress((void**)&T, g_T);
    cudaGetSymbolAddress((void**)&v, g_v);
    cudaGetSymbolAddress((void**)&p, g_p);
    cudaGetSymbolAddress((void**)&o2, g_o2);

    void* h = dlopen("libcuda.so.1", RTLD_NOW | RTLD_GLOBAL);
    if (!h) h = dlopen("libcuda.so", RTLD_NOW | RTLD_GLOBAL);
    EncodeTiledFn enc = (EncodeTiledFn)dlsym(h, "cuTensorMapEncodeTiled");

    const size_t wStride = (size_t)C_ * K2_;
    __nv_bfloat16* wq2 = w2;
    __nv_bfloat16* wv2 = w2 + wStride;
    __nv_bfloat16* wp2 = w2 + 2 * wStride;

    CUtensorMap tm_x2, tm_wq, tm_wv, tm_wp, tm_g2, tm_xt2, tm_o2;
    make_tm(enc, &tm_x2, x2, 32768ull, 2048ull);
    make_tm(enc, &tm_wq, wq2, 1024ull, 2048ull);
    make_tm(enc, &tm_wv, wv2, 1024ull, 2048ull);
    make_tm(enc, &tm_wp, wp2, 1024ull, 2048ull);
    make_tm(enc, &tm_g2, g2, 8192ull, 2048ull);
    make_tm(enc, &tm_xt2, xt2, 8192ull, 8192ull);
    make_tm(enc, &tm_o2, o2, 32768ull, 2048ull);

    auto* kV = gemm_tma<0, 48, false, false, false>;    // V -> fp32 out
    auto* kF = gemm_tma<0, 48, false, true,  false>;    // final + bias
    auto* kG = gemm_tma<1, 192, true, false, true>;     // Gram -> split (+mirror)
    cudaFuncSetAttribute(kV, cudaFuncAttributeMaxDynamicSharedMemorySize, GSMEM_SZ);
    cudaFuncSetAttribute(kF, cudaFuncAttributeMaxDynamicSharedMemorySize, GSMEM_SZ);
    cudaFuncSetAttribute(kG, cudaFuncAttributeMaxDynamicSharedMemorySize, GSMEM_SZ);

    // prep
    split_kernel<<<(C_ * C_ / 4 + 255) / 256, 256>>>((const float4*)Wq, wq2, C_ * C_ / 4);
    split_kernel<<<(C_ * C_ / 4 + 255) / 256, 256>>>((const float4*)Wv, wv2, C_ * C_ / 4);
    split_kernel<<<(C_ * C_ / 4 + 255) / 256, 256>>>((const float4*)Wp, wp2, C_ * C_ / 4);
    prep_x<<<dim3(64, 16, 8), 256>>>(x, x2, xt2);

    // Gram -> split g2 directly (with mirror)
    kG<<<dim3(36, 1, 8), 256, GSMEM_SZ>>>(tm_xt2, tm_xt2, nullptr, g2, C_, C_, 0);

    // V = X Wv^T (fp32 output)
    kV<<<dim3(8, 256, 1), 256, GSMEM_SZ>>>(tm_x2, tm_wv, nullptr, v, 0, 0, 0);

    // T_b = Wq * G_b
    kV<<<dim3(8, 8, 8), 256, GSMEM_SZ>>>(tm_wq, tm_g2, nullptr, T, 0, C_, (size_t)C_ * C_);

    // S + softmax -> P ; then O = P V (split output)
    attn_mid<<<128, 256>>>(T, Wk, p);
    attn_pv<<<512, 256>>>(v, p, o2);

    // out = O' Wp^T + bp
    kF<<<dim3(8, 256, 1), 256, GSMEM_SZ>>>(tm_o2, tm_wp, bp, out, 0, 0, 0);

    dlclose(h);
}

// round 16
// speedup vs baseline: 1.2611x; 1.2228x over previous
#include <cuda_runtime.h>
#include <cuda_bf16.h>
#include <cuda_fp16.h>
#include <cuda.h>
#include <cstdint>
#include <dlfcn.h>

#define B_ 8
#define N_ 4096
#define C_ 1024
#define H_ 16
#define SCALE_ 0.125f
#define M_ (B_ * N_)          // 32768 rows
#define K2_ 2048              // stored split K for 1024-wide operands

// ---------------- scratch ----------------
__device__ __align__(16) __half        g_x2[(size_t)M_ * K2_];          // x split fp16 (hi|lo)
__device__ __align__(16) __nv_bfloat16 g_xt2[(size_t)B_ * C_ * 8192];   // x^T split bf16 per b
__device__ __align__(16) __nv_bfloat16 g_wq2[(size_t)C_ * K2_];         // Wq split bf16
__device__ __align__(16) __half        g_wv2[(size_t)C_ * K2_];         // Wv split fp16
__device__ __align__(16) __half        g_wp2[(size_t)C_ * K2_];         // Wp split fp16
__device__ __align__(16) __nv_bfloat16 g_g2[(size_t)B_ * C_ * K2_];     // G split bf16
__device__ float g_T[(size_t)B_ * C_ * C_];                             // T = Wq G per b
__device__ float g_v[(size_t)M_ * C_];                                  // V = X Wv^T (fp32)
__device__ float g_p[(size_t)128 * 4096];                               // softmaxed P
__device__ __align__(16) __half        g_o2[(size_t)M_ * K2_];          // attn out split fp16

// ---------------- helpers ----------------
__device__ __forceinline__ uint32_t smem_u32(const void* p) {
    uint32_t a;
    asm("{ .reg .u64 t; cvta.to.shared.u64 t, %1; cvt.u32.u64 %0, t; }" : "=r"(a) : "l"(p));
    return a;
}
__device__ __forceinline__ void ldsm4(uint32_t* r, uint32_t addr) {
    asm volatile("ldmatrix.sync.aligned.m8n8.x4.shared.b16 {%0,%1,%2,%3}, [%4];"
                 : "=r"(r[0]), "=r"(r[1]), "=r"(r[2]), "=r"(r[3]) : "r"(addr));
}
__device__ __forceinline__ void mma16816(float* d, const uint32_t* a, uint32_t b0, uint32_t b1) {
    asm volatile("mma.sync.aligned.m16n8k16.row.col.f32.bf16.bf16.f32 "
                 "{%0,%1,%2,%3}, {%4,%5,%6,%7}, {%8,%9}, {%0,%1,%2,%3};"
                 : "+f"(d[0]), "+f"(d[1]), "+f"(d[2]), "+f"(d[3])
                 : "r"(a[0]), "r"(a[1]), "r"(a[2]), "r"(a[3]), "r"(b0), "r"(b1));
}
__device__ __forceinline__ void mma16816h(float* d, const uint32_t* a, uint32_t b0, uint32_t b1) {
    asm volatile("mma.sync.aligned.m16n8k16.row.col.f32.f16.f16.f32 "
                 "{%0,%1,%2,%3}, {%4,%5,%6,%7}, {%8,%9}, {%0,%1,%2,%3};"
                 : "+f"(d[0]), "+f"(d[1]), "+f"(d[2]), "+f"(d[3])
                 : "r"(a[0]), "r"(a[1]), "r"(a[2]), "r"(a[3]), "r"(b0), "r"(b1));
}
__device__ __forceinline__ void mbar_init(uint32_t a, uint32_t cnt) {
    asm volatile("mbarrier.init.shared.b64 [%0], %1;" :: "r"(a), "r"(cnt) : "memory");
}
__device__ __forceinline__ void mbar_wait(uint32_t a, uint32_t parity) {
    asm volatile(
        "{\n\t.reg .pred P;\n\t"
        "W_%=:\n\t"
        "mbarrier.try_wait.parity.acquire.cta.shared::cta.b64 P, [%0], %1, 0x989680;\n\t"
        "@P bra D_%=;\n\t"
        "bra W_%=;\n\t"
        "D_%=:\n\t}"
        :: "r"(a), "r"(parity) : "memory");
}
__device__ __forceinline__ void tma2d(uint32_t smem, const CUtensorMap* tm,
                                      int cx, int cy, uint32_t mbar) {
    asm volatile("cp.async.bulk.tensor.2d.shared::cta.global.tile.mbarrier::complete_tx::bytes "
                 "[%0], [%1, {%2, %3}], [%4];"
                 :: "r"(smem), "l"(tm), "r"(cx), "r"(cy), "r"(mbar) : "memory");
}
__device__ __forceinline__ unsigned long long pk2(float x, float y) {
    unsigned long long r;
    asm("mov.b64 %0, {%1, %2};" : "=l"(r)
        : "r"(__float_as_uint(x)), "r"(__float_as_uint(y)));
    return r;
}
__device__ __forceinline__ void fma2(unsigned long long& c, unsigned long long a,
                                     unsigned long long b) {
    asm("fma.rn.f32x2 %0, %1, %2, %0;" : "+l"(c) : "l"(a), "l"(b));
}
__device__ __forceinline__ float2 upk2(unsigned long long v) {
    unsigned int lo, hi;
    asm("mov.b64 {%0, %1}, %2;" : "=r"(lo), "=r"(hi) : "l"(v));
    return make_float2(__uint_as_float(lo), __uint_as_float(hi));
}
__device__ __forceinline__ void split1(float v, __nv_bfloat16& hi, __nv_bfloat16& lo) {
    hi = __float2bfloat16(v);
    lo = __float2bfloat16(v - __bfloat162float(hi));
}
__device__ __forceinline__ void split1h(float v, __half& hi, __half& lo) {
    hi = __float2half(v);
    lo = __float2half(v - __half2float(hi));
}

// ---------------- split fp32 -> [hi | lo] (rows of 1024) ----------------
__global__ void split_kernel(const float4* __restrict__ in, __nv_bfloat16* __restrict__ out,
                             int n4) {
    int i = blockIdx.x * blockDim.x + threadIdx.x;
    if (i >= n4) return;
    int r = i >> 8;
    int c = (i & 255) << 2;
    float4 v = in[i];
    __nv_bfloat16 hi[4], lo[4];
    split1(v.x, hi[0], lo[0]); split1(v.y, hi[1], lo[1]);
    split1(v.z, hi[2], lo[2]); split1(v.w, hi[3], lo[3]);
    *reinterpret_cast<uint2*>(out + (size_t)r * K2_ + c) = *reinterpret_cast<uint2*>(hi);
    *reinterpret_cast<uint2*>(out + (size_t)r * K2_ + 1024 + c) = *reinterpret_cast<uint2*>(lo);
}
__global__ void split_kernel_h(const float4* __restrict__ in, __half* __restrict__ out,
                               int n4) {
    int i = blockIdx.x * blockDim.x + threadIdx.x;
    if (i >= n4) return;
    int r = i >> 8;
    int c = (i & 255) << 2;
    float4 v = in[i];
    __half hi[4], lo[4];
    split1h(v.x, hi[0], lo[0]); split1h(v.y, hi[1], lo[1]);
    split1h(v.z, hi[2], lo[2]); split1h(v.w, hi[3], lo[3]);
    *reinterpret_cast<uint2*>(out + (size_t)r * K2_ + c) = *reinterpret_cast<uint2*>(hi);
    *reinterpret_cast<uint2*>(out + (size_t)r * K2_ + 1024 + c) = *reinterpret_cast<uint2*>(lo);
}

// ---------------- fused x prep: x2 (fp16 split) + xt2 (bf16 split) ----------------
__global__ __launch_bounds__(256) void prep_x(const float* __restrict__ x,
                                              __half* __restrict__ x2,
                                              __nv_bfloat16* __restrict__ xt) {
    __shared__ float tile[64][65];
    const int b = blockIdx.z;
    const int n0 = blockIdx.x * 64, c0 = blockIdx.y * 64;
    const int tid = threadIdx.x;
    const float* xb = x + ((size_t)b * 4096 + n0) * 1024 + c0;
    {
        int r = tid >> 4, q = tid & 15;
#pragma unroll
        for (int k = 0; k < 4; k++) {
            int rr = r + k * 16;
            float4 v = *reinterpret_cast<const float4*>(xb + (size_t)rr * 1024 + q * 4);
            tile[rr][q * 4 + 0] = v.x; tile[rr][q * 4 + 1] = v.y;
            tile[rr][q * 4 + 2] = v.z; tile[rr][q * 4 + 3] = v.w;
        }
    }
    __syncthreads();
    const int row = tid >> 2, part = tid & 3;
    {   // x2 (fp16): rows = tokens, cols = channels
        __half hi[16], lo[16];
#pragma unroll
        for (int j = 0; j < 16; j++) split1h(tile[row][part * 16 + j], hi[j], lo[j]);
        __half* dst = x2 + ((size_t)b * 4096 + n0 + row) * K2_ + c0 + part * 16;
        *reinterpret_cast<uint4*>(dst)        = *reinterpret_cast<uint4*>(hi);
        *reinterpret_cast<uint4*>(dst + 8)    = *reinterpret_cast<uint4*>(hi + 8);
        *reinterpret_cast<uint4*>(dst + 1024) = *reinterpret_cast<uint4*>(lo);
        *reinterpret_cast<uint4*>(dst + 1032) = *reinterpret_cast<uint4*>(lo + 8);
    }
    {   // xt (bf16): rows = channels, cols = tokens
        __nv_bfloat16 hi[16], lo[16];
#pragma unroll
        for (int j = 0; j < 16; j++) split1(tile[part * 16 + j][row], hi[j], lo[j]);
        __nv_bfloat16* dst = xt + (size_t)b * C_ * 8192 + (size_t)(c0 + row) * 8192 + n0 + part * 16;
        *reinterpret_cast<uint4*>(dst)        = *reinterpret_cast<uint4*>(hi);
        *reinterpret_cast<uint4*>(dst + 8)    = *reinterpret_cast<uint4*>(hi + 8);
        *reinterpret_cast<uint4*>(dst + 4096) = *reinterpret_cast<uint4*>(lo);
        *reinterpret_cast<uint4*>(dst + 4104) = *reinterpret_cast<uint4*>(lo + 8);
    }
}

// ---------------- TMA HMMA split-precision GEMM ----------------
// CMAP 0: bf16 3-term K=1024 (48 chunks). CMAP 1: bf16 Gram K=4096 (192, cols=8192).
// CMAP 2: fp16 2-term K=1024 (32 chunks: hihi + lohi; B is fp16-rounded).
// SYM: triangular tile grid (A==B). GOUT: epilogue writes split-bf16 (mirror only if SYM).
#define STAGE_BYTES 32768
#define GSMEM_SZ (3 * STAGE_BYTES + 64)

template <int CMAP, int NCH, bool SYM, bool BIAS, bool GOUT, bool FP16>
__global__ __launch_bounds__(256, 2) void gemm_tma(
    const __grid_constant__ CUtensorMap tmA, const __grid_constant__ CUtensorMap tmB,
    const float* __restrict__ bias, void* __restrict__ Cptr,
    int aBatchRows, int bBatchRows, size_t cBatch)
{
    extern __shared__ char smem[];
    const uint32_t sb = smem_u32(smem);
    const uint32_t mbb = sb + 3 * STAGE_BYTES;
    const int tid = threadIdx.x, lane = tid & 31, wid = tid >> 5;
    const int wm = wid & 3, wn = wid >> 2;                 // 4 x 2 warp grid (32x64)
    const int z = blockIdx.z;
    int bm, bn;
    if (SYM) {
        int idx = blockIdx.x;
        int ti = (int)floorf((sqrtf(8.f * idx + 1.f) - 1.f) * 0.5f);
        while ((ti + 1) * (ti + 2) / 2 <= idx) ti++;
        while (ti * (ti + 1) / 2 > idx) ti--;
        int tj = idx - ti * (ti + 1) / 2;
        bm = ti * 128; bn = tj * 128;
    } else {
        bm = blockIdx.y * 128;
        bn = blockIdx.x * 128;
    }
    const int cyA = z * aBatchRows + bm;
    const int cyB = z * bBatchRows + bn;

    const int qrow = lane & 15;
    const uint32_t khalf = (uint32_t)((lane >> 4) << 4);
    const uint32_t axor = (uint32_t)((qrow & 7) << 4);

    float acc[2][8][4];
#pragma unroll
    for (int mf = 0; mf < 2; mf++)
#pragma unroll
        for (int nf = 0; nf < 8; nf++)
#pragma unroll
            for (int j = 0; j < 4; j++) acc[mf][nf][j] = 0.f;

    auto kA = [](int i) -> int {
        if (CMAP == 0) return (i < 32 ? i : i - 32) * 64;
        if (CMAP == 2) return (i & 15) * 64 + (i >= 16 ? 1024 : 0);
        int t = i >> 6, j = i & 63;
        return j * 64 + (t == 1 ? 4096 : 0);
    };
    auto kB = [](int i) -> int {
        if (CMAP == 0) return (i < 16 ? i : i - 16) * 64;
        if (CMAP == 2) return (i & 15) * 64;
        int t = i >> 6, j = i & 63;
        return j * 64 + (t == 2 ? 4096 : 0);
    };

    if (tid == 0) {
#pragma unroll
        for (int s = 0; s < 3; s++) mbar_init(mbb + s * 8, 1);
    }
    __syncthreads();

    auto issue = [&](int i) {
        uint32_t st = sb + (uint32_t)(i % 3) * STAGE_BYTES;
        uint32_t mb = mbb + (uint32_t)(i % 3) * 8;
        asm volatile("mbarrier.arrive.expect_tx.shared.b64 _, [%0], %1;"
                     :: "r"(mb), "r"(32768u) : "memory");
        tma2d(st, &tmA, kA(i), cyA, mb);
        tma2d(st + 16384, &tmB, kB(i), cyB, mb);
    };

    if (tid == 0) { issue(0); issue(1); }

    for (int i = 0; i < NCH; i++) {
        mbar_wait(mbb + (i % 3) * 8, (i / 3) & 1);
        __syncthreads();
        if (tid == 0 && i + 2 < NCH) issue(i + 2);

        const uint32_t Ab = sb + (uint32_t)(i % 3) * STAGE_BYTES;
        const uint32_t Bb = Ab + 16384;
#pragma unroll
        for (int ks = 0; ks < 4; ks++) {
            const uint32_t kb = (uint32_t)(ks * 32) + khalf;
            uint32_t af[2][4];
#pragma unroll
            for (int mf = 0; mf < 2; mf++)
                ldsm4(af[mf], Ab + (uint32_t)((wm * 32 + mf * 16 + qrow) * 128) + (kb ^ axor));
#pragma unroll
            for (int np = 0; np < 4; np++) {
                uint32_t r[4];
                ldsm4(r, Bb + (uint32_t)((wn * 64 + np * 16 + qrow) * 128) + (kb ^ axor));
#pragma unroll
                for (int mf = 0; mf < 2; mf++) {
                    if (FP16) {
                        mma16816h(acc[mf][2 * np + 0], af[mf], r[0], r[2]);
                        mma16816h(acc[mf][2 * np + 1], af[mf], r[1], r[3]);
                    } else {
                        mma16816(acc[mf][2 * np + 0], af[mf], r[0], r[2]);
                        mma16816(acc[mf][2 * np + 1], af[mf], r[1], r[3]);
                    }
                }
            }
        }
    }

    if (GOUT) {
        __syncthreads();
        float* st = reinterpret_cast<float*>(smem);
#pragma unroll
        for (int mf = 0; mf < 2; mf++) {
            int r0 = wm * 32 + mf * 16 + (lane >> 2);
#pragma unroll
            for (int nf = 0; nf < 8; nf++) {
                int c = wn * 64 + nf * 8 + (lane & 3) * 2;
                st[r0 * 129 + c]       = acc[mf][nf][0];
                st[r0 * 129 + c + 1]   = acc[mf][nf][1];
                st[(r0 + 8) * 129 + c]     = acc[mf][nf][2];
                st[(r0 + 8) * 129 + c + 1] = acc[mf][nf][3];
            }
        }
        __syncthreads();
        __nv_bfloat16* g2o = reinterpret_cast<__nv_bfloat16*>(Cptr) + (size_t)z * C_ * K2_;
        const int r = tid >> 1, cbase = (tid & 1) * 64;
#pragma unroll
        for (int g = 0; g < 8; g++) {
            __nv_bfloat16 hi[8], lo[8];
#pragma unroll
            for (int j = 0; j < 8; j++)
                split1(st[r * 129 + cbase + g * 8 + j], hi[j], lo[j]);
            size_t base = (size_t)(bm + r) * K2_ + bn + cbase + g * 8;
            *reinterpret_cast<uint4*>(g2o + base) = *reinterpret_cast<uint4*>(hi);
            *reinterpret_cast<uint4*>(g2o + base + 1024) = *reinterpret_cast<uint4*>(lo);
        }
        if (SYM && bm != bn) {
#pragma unroll
            for (int g = 0; g < 8; g++) {
                __nv_bfloat16 hi[8], lo[8];
#pragma unroll
                for (int j = 0; j < 8; j++)
                    split1(st[(cbase + g * 8 + j) * 129 + r], hi[j], lo[j]);
                size_t base = (size_t)(bn + r) * K2_ + bm + cbase + g * 8;
                *reinterpret_cast<uint4*>(g2o + base) = *reinterpret_cast<uint4*>(hi);
                *reinterpret_cast<uint4*>(g2o + base + 1024) = *reinterpret_cast<uint4*>(lo);
            }
        }
    } else {
        float* Cz = reinterpret_cast<float*>(Cptr) + (size_t)z * cBatch;
#pragma unroll
        for (int mf = 0; mf < 2; mf++) {
            const size_t row0 = (size_t)bm + wm * 32 + mf * 16 + (lane >> 2);
#pragma unroll
            for (int nf = 0; nf < 8; nf++) {
                const int col = bn + wn * 64 + nf * 8 + (lane & 3) * 2;
                float bx = 0.f, by = 0.f;
                if (BIAS) { bx = bias[col]; by = bias[col + 1]; }
                *reinterpret_cast<float2*>(Cz + row0 * C_ + col) =
                    make_float2(acc[mf][nf][0] + bx, acc[mf][nf][1] + by);
                *reinterpret_cast<float2*>(Cz + (row0 + 8) * C_ + col) =
                    make_float2(acc[mf][nf][2] + bx, acc[mf][nf][3] + by);
            }
        }
    }
}

// ---------------- attn_mid: S = T_h Wk_h^T (fp32), softmax -> P ----------------
__global__ __launch_bounds__(256) void attn_mid(const float* __restrict__ T,
                                                const float* __restrict__ Wk,
                                                float* __restrict__ P)
{
    __shared__ float Ts[64][68];
    __shared__ float Wks[64][68];
    const int tid = threadIdx.x;
    const int tx = tid & 15, ty = tid >> 4;
    const int bh = blockIdx.x, b = bh >> 4, h = bh & 15;
    const float* Tb  = T + ((size_t)b << 20) + (size_t)(h * 64) * 1024;
    const float* Wkb = Wk + (size_t)(h * 64) * 1024;

    unsigned long long s2[4][2];
#pragma unroll
    for (int i = 0; i < 4; i++) { s2[i][0] = 0ull; s2[i][1] = 0ull; }

    for (int c0 = 0; c0 < 1024; c0 += 64) {
#pragma unroll
        for (int t = 0; t < 4; t++) {
            int fid = tid + t * 256;
            int r  = fid >> 4;
            int c4 = (fid & 15) << 2;
            float4 a = *reinterpret_cast<const float4*>(Tb + (size_t)r * 1024 + c0 + c4);
            Ts[c4 + 0][r] = a.x; Ts[c4 + 1][r] = a.y;
            Ts[c4 + 2][r] = a.z; Ts[c4 + 3][r] = a.w;
            float4 w = *reinterpret_cast<const float4*>(Wkb + (size_t)r * 1024 + c0 + c4);
            Wks[c4 + 0][r] = w.x; Wks[c4 + 1][r] = w.y;
            Wks[c4 + 2][r] = w.z; Wks[c4 + 3][r] = w.w;
        }
        __syncthreads();
#pragma unroll 8
        for (int cc = 0; cc < 64; cc++) {
            float4 a  = *reinterpret_cast<const float4*>(&Ts[cc][tx * 4]);
            float4 bk = *reinterpret_cast<const float4*>(&Wks[cc][ty * 4]);
            unsigned long long e0 = pk2(bk.x, bk.y), e1 = pk2(bk.z, bk.w);
            float av[4] = {a.x, a.y, a.z, a.w};
#pragma unroll
            for (int i = 0; i < 4; i++) {
                unsigned long long ad = pk2(av[i], av[i]);
                fma2(s2[i][0], ad, e0);
                fma2(s2[i][1], ad, e1);
            }
        }
        __syncthreads();
    }

    float* Ss = &Ts[0][0];
#pragma unroll
    for (int i = 0; i < 4; i++) {
        float2 u0 = upk2(s2[i][0]), u1 = upk2(s2[i][1]);
        *reinterpret_cast<float4*>(Ss + (tx * 4 + i) * 64 + ty * 4) =
            make_float4(u0.x * SCALE_, u0.y * SCALE_, u1.x * SCALE_, u1.y * SCALE_);
    }
    __syncthreads();

    {
        int warp = tid >> 5, lane = tid & 31;
        float* p = P + (size_t)bh * 4096;
        for (int r = warp; r < 64; r += 8) {
            float v0 = Ss[r * 64 + lane], v1 = Ss[r * 64 + lane + 32];
            float m = fmaxf(v0, v1);
#pragma unroll
            for (int off = 16; off; off >>= 1) m = fmaxf(m, __shfl_xor_sync(0xffffffffu, m, off));
            float e0 = expf(v0 - m), e1 = expf(v1 - m);
            float ssum = e0 + e1;
#pragma unroll
            for (int off = 16; off; off >>= 1) ssum += __shfl_xor_sync(0xffffffffu, ssum, off);
            float inv = 1.0f / ssum;
            p[r * 64 + lane] = e0 * inv;
            p[r * 64 + lane + 32] = e1 * inv;
        }
    }
}

// ---------------- attn_pv: O-chunk = P * V-chunk, write split fp16 ----------------
__global__ __launch_bounds__(256) void attn_pv(const float* __restrict__ Vbuf,
                                               const float* __restrict__ P,
                                               __half* __restrict__ O2)
{
    __shared__ float Qs[64][64];
    __shared__ float Ks[64][68];
    const int tid = threadIdx.x;
    const int tx = tid & 15, ty = tid >> 4;
    const int bh = blockIdx.x >> 2, ch = blockIdx.x & 3;
    const int b = bh >> 4, h = bh & 15;
    const float* V = Vbuf + (size_t)b * (N_ * C_) + h * 64;
    const int nbase = ch * 1024;

    {
        const float4* ps = reinterpret_cast<const float4*>(P + (size_t)bh * 4096);
#pragma unroll
        for (int t = 0; t < 4; t++) {
            int fid = tid + t * 256;
            *reinterpret_cast<float4*>(&Qs[fid >> 4][(fid & 15) << 2]) = ps[fid];
        }
    }
    __syncthreads();

    for (int n0 = 0; n0 < 1024; n0 += 64) {
#pragma unroll
        for (int t = 0; t < 4; t++) {
            int fid = tid + t * 256;
            int nl  = fid >> 4;
            int e4  = (fid & 15) << 2;
            float4 v = *reinterpret_cast<const float4*>(V + (size_t)(nbase + n0 + nl) * C_ + e4);
            Ks[e4 + 0][nl] = v.x; Ks[e4 + 1][nl] = v.y;
            Ks[e4 + 2][nl] = v.z; Ks[e4 + 3][nl] = v.w;
        }
        __syncthreads();
        unsigned long long o2a[4][2];
#pragma unroll
        for (int i = 0; i < 4; i++) { o2a[i][0] = 0ull; o2a[i][1] = 0ull; }
#pragma unroll 4
        for (int e = 0; e < 64; e += 4) {
            float4 p0 = *reinterpret_cast<const float4*>(&Qs[ty * 4 + 0][e]);
            float4 p1 = *reinterpret_cast<const float4*>(&Qs[ty * 4 + 1][e]);
            float4 p2 = *reinterpret_cast<const float4*>(&Qs[ty * 4 + 2][e]);
            float4 p3 = *reinterpret_cast<const float4*>(&Qs[ty * 4 + 3][e]);
            float4 v0 = *reinterpret_cast<const float4*>(&Ks[e + 0][tx * 4]);
            float4 v1 = *reinterpret_cast<const float4*>(&Ks[e + 1][tx * 4]);
            float4 v2 = *reinterpret_cast<const float4*>(&Ks[e + 2][tx * 4]);
            float4 v3 = *reinterpret_cast<const float4*>(&Ks[e + 3][tx * 4]);
            unsigned long long vq[4][2] = {
                {pk2(v0.x, v0.y), pk2(v0.z, v0.w)},
                {pk2(v1.x, v1.y), pk2(v1.z, v1.w)},
                {pk2(v2.x, v2.y), pk2(v2.z, v2.w)},
                {pk2(v3.x, v3.y), pk2(v3.z, v3.w)}};
            float pr[4][4] = {{p0.x, p0.y, p0.z, p0.w},
                              {p1.x, p1.y, p1.z, p1.w},
                              {p2.x, p2.y, p2.z, p2.w},
                              {p3.x, p3.y, p3.z, p3.w}};
#pragma unroll
            for (int i = 0; i < 4; i++) {
#pragma unroll
                for (int q = 0; q < 4; q++) {
                    unsigned long long pd = pk2(pr[i][q], pr[i][q]);
                    fma2(o2a[i][0], pd, vq[q][0]);
                    fma2(o2a[i][1], pd, vq[q][1]);
                }
            }
        }
        __syncthreads();
#pragma unroll
        for (int i = 0; i < 4; i++) {
            int d = ty * 4 + i;
            size_t row = (size_t)b * 4096 + (size_t)d * 64 + h * 4 + ch;
            int col = n0 + tx * 4;
            float2 u0 = upk2(o2a[i][0]), u1 = upk2(o2a[i][1]);
            float vv[4] = {u0.x, u0.y, u1.x, u1.y};
            __half hi[4], lo[4];
#pragma unroll
            for (int j = 0; j < 4; j++) split1h(vv[j], hi[j], lo[j]);
            *reinterpret_cast<uint2*>(O2 + row * K2_ + col) = *reinterpret_cast<uint2*>(hi);
            *reinterpret_cast<uint2*>(O2 + row * K2_ + 1024 + col) = *reinterpret_cast<uint2*>(lo);
        }
    }
}

// ---------------- host ----------------
typedef CUresult (*EncodeTiledFn)(
    CUtensorMap*, CUtensorMapDataType, cuuint32_t, void*,
    const cuuint64_t*, const cuuint64_t*, const cuuint32_t*, const cuuint32_t*,
    CUtensorMapInterleave, CUtensorMapSwizzle, CUtensorMapL2promotion,
    CUtensorMapFloatOOBfill);

static void make_tm(EncodeTiledFn enc, CUtensorMap* tm, void* ptr,
                    unsigned long long rows, unsigned long long cols,
                    CUtensorMapDataType dt) {
    cuuint64_t dims[2] = {cols, rows};
    cuuint64_t strides[1] = {cols * 2};
    cuuint32_t box[2] = {64, 128};
    cuuint32_t es[2] = {1, 1};
    enc(tm, dt, 2, ptr, dims, strides, box, es,
        CU_TENSOR_MAP_INTERLEAVE_NONE, CU_TENSOR_MAP_SWIZZLE_128B,
        CU_TENSOR_MAP_L2_PROMOTION_L2_128B, CU_TENSOR_MAP_FLOAT_OOB_FILL_NONE);
}

extern "C" void kernel_launch(void* const* d_in, const int* in_sizes, int n_in,
                              void* d_out, int out_size)
{
    const float* x  = (const float*)d_in[0];
    const float* Wq = (const float*)d_in[1];
    const float* Wk = (const float*)d_in[2];
    const float* Wv = (const float*)d_in[3];
    const float* Wp = (const float*)d_in[4];
    const float* bp = (const float*)d_in[5];
    float* out = (float*)d_out;

    __half *x2, *wv2, *wp2, *o2;
    __nv_bfloat16 *xt2, *wq2, *g2;
    float *T, *v, *p;
    cudaGetSymbolAddress((void**)&x2, g_x2);
    cudaGetSymbolAddress((void**)&xt2, g_xt2);
    cudaGetSymbolAddress((void**)&wq2, g_wq2);
    cudaGetSymbolAddress((void**)&wv2, g_wv2);
    cudaGetSymbolAddress((void**)&wp2, g_wp2);
    cudaGetSymbolAddress((void**)&g2, g_g2);
    cudaGetSymbolAddress((void**)&T, g_T);
    cudaGetSymbolAddress((void**)&v, g_v);
    cudaGetSymbolAddress((void**)&p, g_p);
    cudaGetSymbolAddress((void**)&o2, g_o2);

    void* h = dlopen("libcuda.so.1", RTLD_NOW | RTLD_GLOBAL);
    if (!h) h = dlopen("libcuda.so", RTLD_NOW | RTLD_GLOBAL);
    EncodeTiledFn enc = (EncodeTiledFn)dlsym(h, "cuTensorMapEncodeTiled");

    CUtensorMap tm_x2, tm_wq, tm_wv, tm_wp, tm_g2, tm_xt2, tm_o2;
    make_tm(enc, &tm_x2, x2, 32768ull, 2048ull, CU_TENSOR_MAP_DATA_TYPE_FLOAT16);
    make_tm(enc, &tm_wq, wq2, 1024ull, 2048ull, CU_TENSOR_MAP_DATA_TYPE_BFLOAT16);
    make_tm(enc, &tm_wv, wv2, 1024ull, 2048ull, CU_TENSOR_MAP_DATA_TYPE_FLOAT16);
    make_tm(enc, &tm_wp, wp2, 1024ull, 2048ull, CU_TENSOR_MAP_DATA_TYPE_FLOAT16);
    make_tm(enc, &tm_g2, g2, 8192ull, 2048ull, CU_TENSOR_MAP_DATA_TYPE_BFLOAT16);
    make_tm(enc, &tm_xt2, xt2, 8192ull, 8192ull, CU_TENSOR_MAP_DATA_TYPE_BFLOAT16);
    make_tm(enc, &tm_o2, o2, 32768ull, 2048ull, CU_TENSOR_MAP_DATA_TYPE_FLOAT16);

    auto* kV = gemm_tma<2, 32, false, false, false, true>;    // V (fp16 2-term) -> fp32
    auto* kT = gemm_tma<0, 48, false, false, false, false>;   // T (bf16 3-term) -> fp32
    auto* kF = gemm_tma<2, 32, false, true,  false, true>;    // final (fp16 2-term) + bias
    auto* kG = gemm_tma<1, 192, true, false, true, false>;    // Gram (bf16) -> split (+mirror)
    cudaFuncSetAttribute(kV, cudaFuncAttributeMaxDynamicSharedMemorySize, GSMEM_SZ);
    cudaFuncSetAttribute(kT, cudaFuncAttributeMaxDynamicSharedMemorySize, GSMEM_SZ);
    cudaFuncSetAttribute(kF, cudaFuncAttributeMaxDynamicSharedMemorySize, GSMEM_SZ);
    cudaFuncSetAttribute(kG, cudaFuncAttributeMaxDynamicSharedMemorySize, GSMEM_SZ);

    // prep
    split_kernel  <<<(C_ * C_ / 4 + 255) / 256, 256>>>((const float4*)Wq, wq2, C_ * C_ / 4);
    split_kernel_h<<<(C_ * C_ / 4 + 255) / 256, 256>>>((const float4*)Wv, wv2, C_ * C_ / 4);
    split_kernel_h<<<(C_ * C_ / 4 + 255) / 256, 256>>>((const float4*)Wp, wp2, C_ * C_ / 4);
    prep_x<<<dim3(64, 16, 8), 256>>>(x, x2, xt2);

    // Gram -> split g2 directly (with mirror)
    kG<<<dim3(36, 1, 8), 256, GSMEM_SZ>>>(tm_xt2, tm_xt2, nullptr, g2, C_, C_, 0);

    // V = X Wv^T (fp32 output)
    kV<<<dim3(8, 256, 1), 256, GSMEM_SZ>>>(tm_x2, tm_wv, nullptr, v, 0, 0, 0);

    // T_b = Wq * G_b
    kT<<<dim3(8, 8, 8), 256, GSMEM_SZ>>>(tm_wq, tm_g2, nullptr, T, 0, C_, (size_t)C_ * C_);

    // S + softmax -> P ; then O = P V (split fp16 output)
    attn_mid<<<128, 256>>>(T, Wk, p);
    attn_pv<<<512, 256>>>(v, p, o2);

    // out = O' Wp^T + bp
    kF<<<dim3(8, 256, 1), 256, GSMEM_SZ>>>(tm_o2, tm_wp, bp, out, 0, 0, 0);

    dlclose(h);
}

// round 17
// speedup vs baseline: 1.3483x; 1.0692x over previous
#include <cuda_runtime.h>
#include <cuda_bf16.h>
#include <cuda_fp16.h>
#include <cuda.h>
#include <cstdint>
#include <dlfcn.h>

#define B_ 8
#define N_ 4096
#define C_ 1024
#define H_ 16
#define SCALE_ 0.125f
#define M_ (B_ * N_)          // 32768 rows
#define K2_ 2048              // stored split K for 1024-wide operands

// ---------------- scratch ----------------
__device__ __align__(16) __half        g_x2[(size_t)M_ * K2_];          // x split fp16 (hi|lo)
__device__ __align__(16) __half        g_xt2[(size_t)B_ * C_ * 8192];   // x^T split fp16 per b
__device__ __align__(16) __nv_bfloat16 g_wq2[(size_t)C_ * K2_];         // Wq split bf16
__device__ __align__(16) __half        g_wv2[(size_t)C_ * K2_];         // Wv split fp16
__device__ __align__(16) __half        g_wp2[(size_t)C_ * K2_];         // Wp split fp16
__device__ __align__(16) __nv_bfloat16 g_g2[(size_t)B_ * C_ * K2_];     // G split bf16
__device__ float g_T[(size_t)B_ * C_ * C_];                             // T = Wq G per b
__device__ float g_v[(size_t)M_ * C_];                                  // V = X Wv^T (fp32)
__device__ float g_p[(size_t)128 * 4096];                               // softmaxed P
__device__ __align__(16) __half        g_o2[(size_t)M_ * K2_];          // attn out split fp16

// ---------------- helpers ----------------
__device__ __forceinline__ uint32_t smem_u32(const void* p) {
    uint32_t a;
    asm("{ .reg .u64 t; cvta.to.shared.u64 t, %1; cvt.u32.u64 %0, t; }" : "=r"(a) : "l"(p));
    return a;
}
__device__ __forceinline__ void ldsm4(uint32_t* r, uint32_t addr) {
    asm volatile("ldmatrix.sync.aligned.m8n8.x4.shared.b16 {%0,%1,%2,%3}, [%4];"
                 : "=r"(r[0]), "=r"(r[1]), "=r"(r[2]), "=r"(r[3]) : "r"(addr));
}
__device__ __forceinline__ void mma16816(float* d, const uint32_t* a, uint32_t b0, uint32_t b1) {
    asm volatile("mma.sync.aligned.m16n8k16.row.col.f32.bf16.bf16.f32 "
                 "{%0,%1,%2,%3}, {%4,%5,%6,%7}, {%8,%9}, {%0,%1,%2,%3};"
                 : "+f"(d[0]), "+f"(d[1]), "+f"(d[2]), "+f"(d[3])
                 : "r"(a[0]), "r"(a[1]), "r"(a[2]), "r"(a[3]), "r"(b0), "r"(b1));
}
__device__ __forceinline__ void mma16816h(float* d, const uint32_t* a, uint32_t b0, uint32_t b1) {
    asm volatile("mma.sync.aligned.m16n8k16.row.col.f32.f16.f16.f32 "
                 "{%0,%1,%2,%3}, {%4,%5,%6,%7}, {%8,%9}, {%0,%1,%2,%3};"
                 : "+f"(d[0]), "+f"(d[1]), "+f"(d[2]), "+f"(d[3])
                 : "r"(a[0]), "r"(a[1]), "r"(a[2]), "r"(a[3]), "r"(b0), "r"(b1));
}
__device__ __forceinline__ void mbar_init(uint32_t a, uint32_t cnt) {
    asm volatile("mbarrier.init.shared.b64 [%0], %1;" :: "r"(a), "r"(cnt) : "memory");
}
__device__ __forceinline__ void mbar_wait(uint32_t a, uint32_t parity) {
    asm volatile(
        "{\n\t.reg .pred P;\n\t"
        "W_%=:\n\t"
        "mbarrier.try_wait.parity.acquire.cta.shared::cta.b64 P, [%0], %1, 0x989680;\n\t"
        "@P bra D_%=;\n\t"
        "bra W_%=;\n\t"
        "D_%=:\n\t}"
        :: "r"(a), "r"(parity) : "memory");
}
__device__ __forceinline__ void tma2d(uint32_t smem, const CUtensorMap* tm,
                                      int cx, int cy, uint32_t mbar) {
    asm volatile("cp.async.bulk.tensor.2d.shared::cta.global.tile.mbarrier::complete_tx::bytes "
                 "[%0], [%1, {%2, %3}], [%4];"
                 :: "r"(smem), "l"(tm), "r"(cx), "r"(cy), "r"(mbar) : "memory");
}
__device__ __forceinline__ unsigned long long pk2(float x, float y) {
    unsigned long long r;
    asm("mov.b64 %0, {%1, %2};" : "=l"(r)
        : "r"(__float_as_uint(x)), "r"(__float_as_uint(y)));
    return r;
}
__device__ __forceinline__ void fma2(unsigned long long& c, unsigned long long a,
                                     unsigned long long b) {
    asm("fma.rn.f32x2 %0, %1, %2, %0;" : "+l"(c) : "l"(a), "l"(b));
}
__device__ __forceinline__ float2 upk2(unsigned long long v) {
    unsigned int lo, hi;
    asm("mov.b64 {%0, %1}, %2;" : "=r"(lo), "=r"(hi) : "l"(v));
    return make_float2(__uint_as_float(lo), __uint_as_float(hi));
}
__device__ __forceinline__ void split1(float v, __nv_bfloat16& hi, __nv_bfloat16& lo) {
    hi = __float2bfloat16(v);
    lo = __float2bfloat16(v - __bfloat162float(hi));
}
__device__ __forceinline__ void split1h(float v, __half& hi, __half& lo) {
    hi = __float2half(v);
    lo = __float2half(v - __half2float(hi));
}

// ---------------- split fp32 -> [hi | lo] (rows of 1024) ----------------
__global__ void split_kernel(const float4* __restrict__ in, __nv_bfloat16* __restrict__ out,
                             int n4) {
    int i = blockIdx.x * blockDim.x + threadIdx.x;
    if (i >= n4) return;
    int r = i >> 8;
    int c = (i & 255) << 2;
    float4 v = in[i];
    __nv_bfloat16 hi[4], lo[4];
    split1(v.x, hi[0], lo[0]); split1(v.y, hi[1], lo[1]);
    split1(v.z, hi[2], lo[2]); split1(v.w, hi[3], lo[3]);
    *reinterpret_cast<uint2*>(out + (size_t)r * K2_ + c) = *reinterpret_cast<uint2*>(hi);
    *reinterpret_cast<uint2*>(out + (size_t)r * K2_ + 1024 + c) = *reinterpret_cast<uint2*>(lo);
}
__global__ void split_kernel_h(const float4* __restrict__ in, __half* __restrict__ out,
                               int n4) {
    int i = blockIdx.x * blockDim.x + threadIdx.x;
    if (i >= n4) return;
    int r = i >> 8;
    int c = (i & 255) << 2;
    float4 v = in[i];
    __half hi[4], lo[4];
    split1h(v.x, hi[0], lo[0]); split1h(v.y, hi[1], lo[1]);
    split1h(v.z, hi[2], lo[2]); split1h(v.w, hi[3], lo[3]);
    *reinterpret_cast<uint2*>(out + (size_t)r * K2_ + c) = *reinterpret_cast<uint2*>(hi);
    *reinterpret_cast<uint2*>(out + (size_t)r * K2_ + 1024 + c) = *reinterpret_cast<uint2*>(lo);
}

// ---------------- fused x prep: x2 (fp16 split) + xt2 (fp16 split) ----------------
__global__ __launch_bounds__(256) void prep_x(const float* __restrict__ x,
                                              __half* __restrict__ x2,
                                              __half* __restrict__ xt) {
    __shared__ float tile[64][65];
    const int b = blockIdx.z;
    const int n0 = blockIdx.x * 64, c0 = blockIdx.y * 64;
    const int tid = threadIdx.x;
    const float* xb = x + ((size_t)b * 4096 + n0) * 1024 + c0;
    {
        int r = tid >> 4, q = tid & 15;
#pragma unroll
        for (int k = 0; k < 4; k++) {
            int rr = r + k * 16;
            float4 v = *reinterpret_cast<const float4*>(xb + (size_t)rr * 1024 + q * 4);
            tile[rr][q * 4 + 0] = v.x; tile[rr][q * 4 + 1] = v.y;
            tile[rr][q * 4 + 2] = v.z; tile[rr][q * 4 + 3] = v.w;
        }
    }
    __syncthreads();
    const int row = tid >> 2, part = tid & 3;
    {   // x2 (fp16): rows = tokens, cols = channels
        __half hi[16], lo[16];
#pragma unroll
        for (int j = 0; j < 16; j++) split1h(tile[row][part * 16 + j], hi[j], lo[j]);
        __half* dst = x2 + ((size_t)b * 4096 + n0 + row) * K2_ + c0 + part * 16;
        *reinterpret_cast<uint4*>(dst)        = *reinterpret_cast<uint4*>(hi);
        *reinterpret_cast<uint4*>(dst + 8)    = *reinterpret_cast<uint4*>(hi + 8);
        *reinterpret_cast<uint4*>(dst + 1024) = *reinterpret_cast<uint4*>(lo);
        *reinterpret_cast<uint4*>(dst + 1032) = *reinterpret_cast<uint4*>(lo + 8);
    }
    {   // xt (fp16): rows = channels, cols = tokens
        __half hi[16], lo[16];
#pragma unroll
        for (int j = 0; j < 16; j++) split1h(tile[part * 16 + j][row], hi[j], lo[j]);
        __half* dst = xt + (size_t)b * C_ * 8192 + (size_t)(c0 + row) * 8192 + n0 + part * 16;
        *reinterpret_cast<uint4*>(dst)        = *reinterpret_cast<uint4*>(hi);
        *reinterpret_cast<uint4*>(dst + 8)    = *reinterpret_cast<uint4*>(hi + 8);
        *reinterpret_cast<uint4*>(dst + 4096) = *reinterpret_cast<uint4*>(lo);
        *reinterpret_cast<uint4*>(dst + 4104) = *reinterpret_cast<uint4*>(lo + 8);
    }
}

// ---------------- TMA HMMA split-precision GEMM ----------------
// CMAP 0: bf16 3-term K=1024 (48 chunks). CMAP 1: bf16 Gram K=4096 (192, cols=8192).
// CMAP 2: fp16 2-term K=1024 (32 chunks). CMAP 3: fp16 2-term Gram K=4096 (128, cols=8192).
// SYM: triangular tile grid (A==B). GOUT: epilogue writes split-bf16 (mirror only if SYM).
#define STAGE_BYTES 32768
#define GSMEM_SZ (3 * STAGE_BYTES + 64)

template <int CMAP, int NCH, bool SYM, bool BIAS, bool GOUT, bool FP16>
__global__ __launch_bounds__(256, 2) void gemm_tma(
    const __grid_constant__ CUtensorMap tmA, const __grid_constant__ CUtensorMap tmB,
    const float* __restrict__ bias, void* __restrict__ Cptr,
    int aBatchRows, int bBatchRows, size_t cBatch)
{
    extern __shared__ char smem[];
    const uint32_t sb = smem_u32(smem);
    const uint32_t mbb = sb + 3 * STAGE_BYTES;
    const int tid = threadIdx.x, lane = tid & 31, wid = tid >> 5;
    const int wm = wid & 3, wn = wid >> 2;                 // 4 x 2 warp grid (32x64)
    const int z = blockIdx.z;
    int bm, bn;
    if (SYM) {
        int idx = blockIdx.x;
        int ti = (int)floorf((sqrtf(8.f * idx + 1.f) - 1.f) * 0.5f);
        while ((ti + 1) * (ti + 2) / 2 <= idx) ti++;
        while (ti * (ti + 1) / 2 > idx) ti--;
        int tj = idx - ti * (ti + 1) / 2;
        bm = ti * 128; bn = tj * 128;
    } else {
        bm = blockIdx.y * 128;
        bn = blockIdx.x * 128;
    }
    const int cyA = z * aBatchRows + bm;
    const int cyB = z * bBatchRows + bn;

    const int qrow = lane & 15;
    const uint32_t khalf = (uint32_t)((lane >> 4) << 4);
    const uint32_t axor = (uint32_t)((qrow & 7) << 4);

    float acc[2][8][4];
#pragma unroll
    for (int mf = 0; mf < 2; mf++)
#pragma unroll
        for (int nf = 0; nf < 8; nf++)
#pragma unroll
            for (int j = 0; j < 4; j++) acc[mf][nf][j] = 0.f;

    auto kA = [](int i) -> int {
        if (CMAP == 0) return (i < 32 ? i : i - 32) * 64;
        if (CMAP == 2) return (i & 15) * 64 + (i >= 16 ? 1024 : 0);
        if (CMAP == 3) return (i & 63) * 64 + (i >= 64 ? 4096 : 0);
        int t = i >> 6, j = i & 63;
        return j * 64 + (t == 1 ? 4096 : 0);
    };
    auto kB = [](int i) -> int {
        if (CMAP == 0) return (i < 16 ? i : i - 16) * 64;
        if (CMAP == 2) return (i & 15) * 64;
        if (CMAP == 3) return (i & 63) * 64;
        int t = i >> 6, j = i & 63;
        return j * 64 + (t == 2 ? 4096 : 0);
    };

    if (tid == 0) {
#pragma unroll
        for (int s = 0; s < 3; s++) mbar_init(mbb + s * 8, 1);
    }
    __syncthreads();

    auto issue = [&](int i) {
        uint32_t st = sb + (uint32_t)(i % 3) * STAGE_BYTES;
        uint32_t mb = mbb + (uint32_t)(i % 3) * 8;
        asm volatile("mbarrier.arrive.expect_tx.shared.b64 _, [%0], %1;"
                     :: "r"(mb), "r"(32768u) : "memory");
        tma2d(st, &tmA, kA(i), cyA, mb);
        tma2d(st + 16384, &tmB, kB(i), cyB, mb);
    };

    if (tid == 0) { issue(0); issue(1); }

    for (int i = 0; i < NCH; i++) {
        mbar_wait(mbb + (i % 3) * 8, (i / 3) & 1);
        __syncthreads();
        if (tid == 0 && i + 2 < NCH) issue(i + 2);

        const uint32_t Ab = sb + (uint32_t)(i % 3) * STAGE_BYTES;
        const uint32_t Bb = Ab + 16384;
#pragma unroll
        for (int ks = 0; ks < 4; ks++) {
            const uint32_t kb = (uint32_t)(ks * 32) + khalf;
            uint32_t af[2][4];
#pragma unroll
            for (int mf = 0; mf < 2; mf++)
                ldsm4(af[mf], Ab + (uint32_t)((wm * 32 + mf * 16 + qrow) * 128) + (kb ^ axor));
#pragma unroll
            for (int np = 0; np < 4; np++) {
                uint32_t r[4];
                ldsm4(r, Bb + (uint32_t)((wn * 64 + np * 16 + qrow) * 128) + (kb ^ axor));
#pragma unroll
                for (int mf = 0; mf < 2; mf++) {
                    if (FP16) {
                        mma16816h(acc[mf][2 * np + 0], af[mf], r[0], r[2]);
                        mma16816h(acc[mf][2 * np + 1], af[mf], r[1], r[3]);
                    } else {
                        mma16816(acc[mf][2 * np + 0], af[mf], r[0], r[2]);
                        mma16816(acc[mf][2 * np + 1], af[mf], r[1], r[3]);
                    }
                }
            }
        }
    }

    if (GOUT) {
        __syncthreads();
        float* st = reinterpret_cast<float*>(smem);
#pragma unroll
        for (int mf = 0; mf < 2; mf++) {
            int r0 = wm * 32 + mf * 16 + (lane >> 2);
#pragma unroll
            for (int nf = 0; nf < 8; nf++) {
                int c = wn * 64 + nf * 8 + (lane & 3) * 2;
                st[r0 * 129 + c]       = acc[mf][nf][0];
                st[r0 * 129 + c + 1]   = acc[mf][nf][1];
                st[(r0 + 8) * 129 + c]     = acc[mf][nf][2];
                st[(r0 + 8) * 129 + c + 1] = acc[mf][nf][3];
            }
        }
        __syncthreads();
        __nv_bfloat16* g2o = reinterpret_cast<__nv_bfloat16*>(Cptr) + (size_t)z * C_ * K2_;
        const int r = tid >> 1, cbase = (tid & 1) * 64;
#pragma unroll
        for (int g = 0; g < 8; g++) {
            __nv_bfloat16 hi[8], lo[8];
#pragma unroll
            for (int j = 0; j < 8; j++)
                split1(st[r * 129 + cbase + g * 8 + j], hi[j], lo[j]);
            size_t base = (size_t)(bm + r) * K2_ + bn + cbase + g * 8;
            *reinterpret_cast<uint4*>(g2o + base) = *reinterpret_cast<uint4*>(hi);
            *reinterpret_cast<uint4*>(g2o + base + 1024) = *reinterpret_cast<uint4*>(lo);
        }
        if (SYM && bm != bn) {
#pragma unroll
            for (int g = 0; g < 8; g++) {
                __nv_bfloat16 hi[8], lo[8];
#pragma unroll
                for (int j = 0; j < 8; j++)
                    split1(st[(cbase + g * 8 + j) * 129 + r], hi[j], lo[j]);
                size_t base = (size_t)(bn + r) * K2_ + bm + cbase + g * 8;
                *reinterpret_cast<uint4*>(g2o + base) = *reinterpret_cast<uint4*>(hi);
                *reinterpret_cast<uint4*>(g2o + base + 1024) = *reinterpret_cast<uint4*>(lo);
            }
        }
    } else {
        float* Cz = reinterpret_cast<float*>(Cptr) + (size_t)z * cBatch;
#pragma unroll
        for (int mf = 0; mf < 2; mf++) {
            const size_t row0 = (size_t)bm + wm * 32 + mf * 16 + (lane >> 2);
#pragma unroll
            for (int nf = 0; nf < 8; nf++) {
                const int col = bn + wn * 64 + nf * 8 + (lane & 3) * 2;
                float bx = 0.f, by = 0.f;
                if (BIAS) { bx = bias[col]; by = bias[col + 1]; }
                *reinterpret_cast<float2*>(Cz + row0 * C_ + col) =
                    make_float2(acc[mf][nf][0] + bx, acc[mf][nf][1] + by);
                *reinterpret_cast<float2*>(Cz + (row0 + 8) * C_ + col) =
                    make_float2(acc[mf][nf][2] + bx, acc[mf][nf][3] + by);
            }
        }
    }
}

// ---------------- attn_mid: S = T_h Wk_h^T (fp32), softmax -> P ----------------
__global__ __launch_bounds__(256) void attn_mid(const float* __restrict__ T,
                                                const float* __restrict__ Wk,
                                                float* __restrict__ P)
{
    __shared__ float Ts[64][68];
    __shared__ float Wks[64][68];
    const int tid = threadIdx.x;
    const int tx = tid & 15, ty = tid >> 4;
    const int bh = blockIdx.x, b = bh >> 4, h = bh & 15;
    const float* Tb  = T + ((size_t)b << 20) + (size_t)(h * 64) * 1024;
    const float* Wkb = Wk + (size_t)(h * 64) * 1024;

    unsigned long long s2[4][2];
#pragma unroll
    for (int i = 0; i < 4; i++) { s2[i][0] = 0ull; s2[i][1] = 0ull; }

    for (int c0 = 0; c0 < 1024; c0 += 64) {
#pragma unroll
        for (int t = 0; t < 4; t++) {
            int fid = tid + t * 256;
            int r  = fid >> 4;
            int c4 = (fid & 15) << 2;
            float4 a = *reinterpret_cast<const float4*>(Tb + (size_t)r * 1024 + c0 + c4);
            Ts[c4 + 0][r] = a.x; Ts[c4 + 1][r] = a.y;
            Ts[c4 + 2][r] = a.z; Ts[c4 + 3][r] = a.w;
            float4 w = *reinterpret_cast<const float4*>(Wkb + (size_t)r * 1024 + c0 + c4);
            Wks[c4 + 0][r] = w.x; Wks[c4 + 1][r] = w.y;
            Wks[c4 + 2][r] = w.z; Wks[c4 + 3][r] = w.w;
        }
        __syncthreads();
#pragma unroll 8
        for (int cc = 0; cc < 64; cc++) {
            float4 a  = *reinterpret_cast<const float4*>(&Ts[cc][tx * 4]);
            float4 bk = *reinterpret_cast<const float4*>(&Wks[cc][ty * 4]);
            unsigned long long e0 = pk2(bk.x, bk.y), e1 = pk2(bk.z, bk.w);
            float av[4] = {a.x, a.y, a.z, a.w};
#pragma unroll
            for (int i = 0; i < 4; i++) {
                unsigned long long ad = pk2(av[i], av[i]);
                fma2(s2[i][0], ad, e0);
                fma2(s2[i][1], ad, e1);
            }
        }
        __syncthreads();
    }

    float* Ss = &Ts[0][0];
#pragma unroll
    for (int i = 0; i < 4; i++) {
        float2 u0 = upk2(s2[i][0]), u1 = upk2(s2[i][1]);
        *reinterpret_cast<float4*>(Ss + (tx * 4 + i) * 64 + ty * 4) =
            make_float4(u0.x * SCALE_, u0.y * SCALE_, u1.x * SCALE_, u1.y * SCALE_);
    }
    __syncthreads();

    {
        int warp = tid >> 5, lane = tid & 31;
        float* p = P + (size_t)bh * 4096;
        for (int r = warp; r < 64; r += 8) {
            float v0 = Ss[r * 64 + lane], v1 = Ss[r * 64 + lane + 32];
            float m = fmaxf(v0, v1);
#pragma unroll
            for (int off = 16; off; off >>= 1) m = fmaxf(m, __shfl_xor_sync(0xffffffffu, m, off));
            float e0 = expf(v0 - m), e1 = expf(v1 - m);
            float ssum = e0 + e1;
#pragma unroll
            for (int off = 16; off; off >>= 1) ssum += __shfl_xor_sync(0xffffffffu, ssum, off);
            float inv = 1.0f / ssum;
            p[r * 64 + lane] = e0 * inv;
            p[r * 64 + lane + 32] = e1 * inv;
        }
    }
}

// ---------------- attn_pv: O-chunk = P * V-chunk, write split fp16 ----------------
__global__ __launch_bounds__(256) void attn_pv(const float* __restrict__ Vbuf,
                                               const float* __restrict__ P,
                                               __half* __restrict__ O2)
{
    __shared__ float Qs[64][64];
    __shared__ float Ks[64][68];
    const int tid = threadIdx.x;
    const int tx = tid & 15, ty = tid >> 4;
    const int bh = blockIdx.x >> 2, ch = blockIdx.x & 3;
    const int b = bh >> 4, h = bh & 15;
    const float* V = Vbuf + (size_t)b * (N_ * C_) + h * 64;
    const int nbase = ch * 1024;

    {
        const float4* ps = reinterpret_cast<const float4*>(P + (size_t)bh * 4096);
#pragma unroll
        for (int t = 0; t < 4; t++) {
            int fid = tid + t * 256;
            *reinterpret_cast<float4*>(&Qs[fid >> 4][(fid & 15) << 2]) = ps[fid];
        }
    }
    __syncthreads();

    for (int n0 = 0; n0 < 1024; n0 += 64) {
#pragma unroll
        for (int t = 0; t < 4; t++) {
            int fid = tid + t * 256;
            int nl  = fid >> 4;
            int e4  = (fid & 15) << 2;
            float4 v = *reinterpret_cast<const float4*>(V + (size_t)(nbase + n0 + nl) * C_ + e4);
            Ks[e4 + 0][nl] = v.x; Ks[e4 + 1][nl] = v.y;
            Ks[e4 + 2][nl] = v.z; Ks[e4 + 3][nl] = v.w;
        }
        __syncthreads();
        unsigned long long o2a[4][2];
#pragma unroll
        for (int i = 0; i < 4; i++) { o2a[i][0] = 0ull; o2a[i][1] = 0ull; }
#pragma unroll 4
        for (int e = 0; e < 64; e += 4) {
            float4 p0 = *reinterpret_cast<const float4*>(&Qs[ty * 4 + 0][e]);
            float4 p1 = *reinterpret_cast<const float4*>(&Qs[ty * 4 + 1][e]);
            float4 p2 = *reinterpret_cast<const float4*>(&Qs[ty * 4 + 2][e]);
            float4 p3 = *reinterpret_cast<const float4*>(&Qs[ty * 4 + 3][e]);
            float4 v0 = *reinterpret_cast<const float4*>(&Ks[e + 0][tx * 4]);
            float4 v1 = *reinterpret_cast<const float4*>(&Ks[e + 1][tx * 4]);
            float4 v2 = *reinterpret_cast<const float4*>(&Ks[e + 2][tx * 4]);
            float4 v3 = *reinterpret_cast<const float4*>(&Ks[e + 3][tx * 4]);
            unsigned long long vq[4][2] = {
                {pk2(v0.x, v0.y), pk2(v0.z, v0.w)},
                {pk2(v1.x, v1.y), pk2(v1.z, v1.w)},
                {pk2(v2.x, v2.y), pk2(v2.z, v2.w)},
                {pk2(v3.x, v3.y), pk2(v3.z, v3.w)}};
            float pr[4][4] = {{p0.x, p0.y, p0.z, p0.w},
                              {p1.x, p1.y, p1.z, p1.w},
                              {p2.x, p2.y, p2.z, p2.w},
                              {p3.x, p3.y, p3.z, p3.w}};
#pragma unroll
            for (int i = 0; i < 4; i++) {
#pragma unroll
                for (int q = 0; q < 4; q++) {
                    unsigned long long pd = pk2(pr[i][q], pr[i][q]);
                    fma2(o2a[i][0], pd, vq[q][0]);
                    fma2(o2a[i][1], pd, vq[q][1]);
                }
            }
        }
        __syncthreads();
#pragma unroll
        for (int i = 0; i < 4; i++) {
            int d = ty * 4 + i;
            size_t row = (size_t)b * 4096 + (size_t)d * 64 + h * 4 + ch;
            int col = n0 + tx * 4;
            float2 u0 = upk2(o2a[i][0]), u1 = upk2(o2a[i][1]);
            float vv[4] = {u0.x, u0.y, u1.x, u1.y};
            __half hi[4], lo[4];
#pragma unroll
            for (int j = 0; j < 4; j++) split1h(vv[j], hi[j], lo[j]);
            *reinterpret_cast<uint2*>(O2 + row * K2_ + col) = *reinterpret_cast<uint2*>(hi);
            *reinterpret_cast<uint2*>(O2 + row * K2_ + 1024 + col) = *reinterpret_cast<uint2*>(lo);
        }
    }
}

// ---------------- host ----------------
typedef CUresult (*EncodeTiledFn)(
    CUtensorMap*, CUtensorMapDataType, cuuint32_t, void*,
    const cuuint64_t*, const cuuint64_t*, const cuuint32_t*, const cuuint32_t*,
    CUtensorMapInterleave, CUtensorMapSwizzle, CUtensorMapL2promotion,
    CUtensorMapFloatOOBfill);

static void make_tm(EncodeTiledFn enc, CUtensorMap* tm, void* ptr,
                    unsigned long long rows, unsigned long long cols,
                    CUtensorMapDataType dt) {
    cuuint64_t dims[2] = {cols, rows};
    cuuint64_t strides[1] = {cols * 2};
    cuuint32_t box[2] = {64, 128};
    cuuint32_t es[2] = {1, 1};
    enc(tm, dt, 2, ptr, dims, strides, box, es,
        CU_TENSOR_MAP_INTERLEAVE_NONE, CU_TENSOR_MAP_SWIZZLE_128B,
        CU_TENSOR_MAP_L2_PROMOTION_L2_128B, CU_TENSOR_MAP_FLOAT_OOB_FILL_NONE);
}

extern "C" void kernel_launch(void* const* d_in, const int* in_sizes, int n_in,
                              void* d_out, int out_size)
{
    const float* x  = (const float*)d_in[0];
    const float* Wq = (const float*)d_in[1];
    const float* Wk = (const float*)d_in[2];
    const float* Wv = (const float*)d_in[3];
    const float* Wp = (const float*)d_in[4];
    const float* bp = (const float*)d_in[5];
    float* out = (float*)d_out;

    __half *x2, *xt2, *wv2, *wp2, *o2;
    __nv_bfloat16 *wq2, *g2;
    float *T, *v, *p;
    cudaGetSymbolAddress((void**)&x2, g_x2);
    cudaGetSymbolAddress((void**)&xt2, g_xt2);
    cudaGetSymbolAddress((void**)&wq2, g_wq2);
    cudaGetSymbolAddress((void**)&wv2, g_wv2);
    cudaGetSymbolAddress((void**)&wp2, g_wp2);
    cudaGetSymbolAddress((void**)&g2, g_g2);
    cudaGetSymbolAddress((void**)&T, g_T);
    cudaGetSymbolAddress((void**)&v, g_v);
    cudaGetSymbolAddress((void**)&p, g_p);
    cudaGetSymbolAddress((void**)&o2, g_o2);

    void* h = dlopen("libcuda.so.1", RTLD_NOW | RTLD_GLOBAL);
    if (!h) h = dlopen("libcuda.so", RTLD_NOW | RTLD_GLOBAL);
    EncodeTiledFn enc = (EncodeTiledFn)dlsym(h, "cuTensorMapEncodeTiled");

    CUtensorMap tm_x2, tm_wq, tm_wv, tm_wp, tm_g2, tm_xt2, tm_o2;
    make_tm(enc, &tm_x2, x2, 32768ull, 2048ull, CU_TENSOR_MAP_DATA_TYPE_FLOAT16);
    make_tm(enc, &tm_wq, wq2, 1024ull, 2048ull, CU_TENSOR_MAP_DATA_TYPE_BFLOAT16);
    make_tm(enc, &tm_wv, wv2, 1024ull, 2048ull, CU_TENSOR_MAP_DATA_TYPE_FLOAT16);
    make_tm(enc, &tm_wp, wp2, 1024ull, 2048ull, CU_TENSOR_MAP_DATA_TYPE_FLOAT16);
    make_tm(enc, &tm_g2, g2, 8192ull, 2048ull, CU_TENSOR_MAP_DATA_TYPE_BFLOAT16);
    make_tm(enc, &tm_xt2, xt2, 8192ull, 8192ull, CU_TENSOR_MAP_DATA_TYPE_FLOAT16);
    make_tm(enc, &tm_o2, o2, 32768ull, 2048ull, CU_TENSOR_MAP_DATA_TYPE_FLOAT16);

    auto* kV = gemm_tma<2, 32, false, false, false, true>;    // V (fp16 2-term) -> fp32
    auto* kT = gemm_tma<0, 48, false, false, false, false>;   // T (bf16 3-term) -> fp32
    auto* kF = gemm_tma<2, 32, false, true,  false, true>;    // final (fp16 2-term) + bias
    auto* kG = gemm_tma<3, 128, true, false, true, true>;     // Gram (fp16 2-term) -> bf16 split
    cudaFuncSetAttribute(kV, cudaFuncAttributeMaxDynamicSharedMemorySize, GSMEM_SZ);
    cudaFuncSetAttribute(kT, cudaFuncAttributeMaxDynamicSharedMemorySize, GSMEM_SZ);
    cudaFuncSetAttribute(kF, cudaFuncAttributeMaxDynamicSharedMemorySize, GSMEM_SZ);
    cudaFuncSetAttribute(kG, cudaFuncAttributeMaxDynamicSharedMemorySize, GSMEM_SZ);

    // prep
    split_kernel  <<<(C_ * C_ / 4 + 255) / 256, 256>>>((const float4*)Wq, wq2, C_ * C_ / 4);
    split_kernel_h<<<(C_ * C_ / 4 + 255) / 256, 256>>>((const float4*)Wv, wv2, C_ * C_ / 4);
    split_kernel_h<<<(C_ * C_ / 4 + 255) / 256, 256>>>((const float4*)Wp, wp2, C_ * C_ / 4);
    prep_x<<<dim3(64, 16, 8), 256>>>(x, x2, xt2);

    // Gram (fp16 2-term MMA, fp32 acc) -> bf16 split g2 (with mirror)
    kG<<<dim3(36, 1, 8), 256, GSMEM_SZ>>>(tm_xt2, tm_xt2, nullptr, g2, C_, C_, 0);

    // V = X Wv^T (fp32 output)
    kV<<<dim3(8, 256, 1), 256, GSMEM_SZ>>>(tm_x2, tm_wv, nullptr, v, 0, 0, 0);

    // T_b = Wq * G_b (bf16 3-term)
    kT<<<dim3(8, 8, 8), 256, GSMEM_SZ>>>(tm_wq, tm_g2, nullptr, T, 0, C_, (size_t)C_ * C_);

    // S + softmax -> P ; then O = P V (split fp16 output)
    attn_mid<<<128, 256>>>(T, Wk, p);
    attn_pv<<<512, 256>>>(v, p, o2);

    // out = O' Wp^T + bp
    kF<<<dim3(8, 256, 1), 256, GSMEM_SZ>>>(tm_o2, tm_wp, bp, out, 0, 0, 0);

    dlclose(h);
}